// round 9
// baseline (speedup 1.0000x reference)
#include <cuda_runtime.h>
#include <cuda_bf16.h>
#include <cstdint>

#define N_NODES 255
#define NNZ_E   2550
#define BATCH   512
#define M_ROWS  (BATCH * N_NODES)   // 130560 (divisible by 128)
#define MAXD    400
#define MAXKPAD 448

// ---------------- device scratch (no allocations allowed) ----------------
__device__ __align__(256) float         g_bufA[M_ROWS * MAXD];
__device__ __align__(256) float         g_bufB[M_ROWS * MAXD];
__device__ __align__(256) __nv_bfloat16 g_hi[M_ROWS * MAXKPAD];
__device__ __align__(256) __nv_bfloat16 g_lo[M_ROWS * MAXKPAD];
__device__ __align__(256) __nv_bfloat16 g_wstack[520192];   // max Npad*3*Kpad
__device__ int   g_rowptr[2][N_NODES + 1];
__device__ int   g_cols[2][NNZ_E];
__device__ float g_vals[2][NNZ_E];
__device__ float g_rowsum[2][N_NODES];

// ================= PTX helpers =================
__device__ __forceinline__ uint32_t smem_u32(const void* p) {
    uint32_t a;
    asm("{ .reg .u64 t; cvta.to.shared.u64 t, %1; cvt.u32.u64 %0, t; }" : "=r"(a) : "l"(p));
    return a;
}
__device__ __forceinline__ void ldmx4(uint32_t& r0, uint32_t& r1, uint32_t& r2, uint32_t& r3,
                                      uint32_t addr) {
    asm volatile("ldmatrix.sync.aligned.m8n8.x4.shared.b16 {%0,%1,%2,%3}, [%4];"
                 : "=r"(r0), "=r"(r1), "=r"(r2), "=r"(r3) : "r"(addr));
}
__device__ __forceinline__ void mma16816(float* d, const uint32_t* a, const uint32_t* b) {
    asm volatile(
        "mma.sync.aligned.m16n8k16.row.col.f32.bf16.bf16.f32 "
        "{%0,%1,%2,%3}, {%4,%5,%6,%7}, {%8,%9}, {%0,%1,%2,%3};"
        : "+f"(d[0]), "+f"(d[1]), "+f"(d[2]), "+f"(d[3])
        : "r"(a[0]), "r"(a[1]), "r"(a[2]), "r"(a[3]), "r"(b[0]), "r"(b[1]));
}
__device__ __forceinline__ void cpasync16(uint32_t dst, const void* src) {
    asm volatile("cp.async.cg.shared.global [%0], [%1], 16;" :: "r"(dst), "l"(src) : "memory");
}
__device__ __forceinline__ void cp_commit() {
    asm volatile("cp.async.commit_group;" ::: "memory");
}

// ---------------- deterministic COO -> CSR build (1 block per matrix) ----
__global__ void build_csr_kernel(const int* __restrict__ sm_idx, const float* __restrict__ sm_val,
                                 const int* __restrict__ sp_idx, const float* __restrict__ sp_val) {
    __shared__ int   srow[NNZ_E];
    __shared__ float sval[NNZ_E];
    __shared__ int   rptr[N_NODES + 1];
    __shared__ int   cnt[N_NODES];
    const int mat = blockIdx.x;
    const int*   idx = mat ? sp_idx : sm_idx;
    const float* val = mat ? sp_val : sm_val;
    const int t = threadIdx.x;

    for (int e = t; e < NNZ_E; e += blockDim.x) { srow[e] = idx[2 * e]; sval[e] = val[e]; }
    for (int i = t; i < N_NODES; i += blockDim.x) cnt[i] = 0;
    __syncthreads();
    for (int e = t; e < NNZ_E; e += blockDim.x) atomicAdd(&cnt[srow[e]], 1);
    __syncthreads();
    if (t == 0) {
        int s = 0;
        for (int i = 0; i < N_NODES; i++) { rptr[i] = s; s += cnt[i]; }
        rptr[N_NODES] = s;
    }
    __syncthreads();
    for (int e = t; e < NNZ_E; e += blockDim.x) {
        const int r = srow[e];
        int rank = 0;
        for (int e2 = 0; e2 < e; e2++) rank += (srow[e2] == r) ? 1 : 0;
        const int slot = rptr[r] + rank;
        g_cols[mat][slot] = idx[2 * e + 1];
        g_vals[mat][slot] = sval[e];
    }
    for (int i = t; i <= N_NODES; i += blockDim.x) g_rowptr[mat][i] = rptr[i];
    for (int i = t; i < N_NODES; i += blockDim.x) {
        float s = 0.f;
        for (int e = 0; e < NNZ_E; e++)
            if (srow[e] == i) s += sval[e];
        g_rowsum[mat][i] = s;
    }
}

// ---------------- SpMM, feature dim = 2 ----------------------------------
__global__ void spmm_d2_kernel(int mat, const float* __restrict__ X,
                               float* __restrict__ out, int relu) {
    const int t = blockIdx.x * blockDim.x + threadIdx.x;
    if (t >= M_ROWS) return;
    const int b = t / N_NODES;
    const int i = t - b * N_NODES;
    const int p0 = g_rowptr[mat][i], p1 = g_rowptr[mat][i + 1];
    const float2* Xb = reinterpret_cast<const float2*>(X) + (size_t)b * N_NODES;
    float a0 = 0.f, a1 = 0.f;
    for (int e = p0; e < p1; e++) {
        const float v = g_vals[mat][e];
        const float2 x = Xb[g_cols[mat][e]];
        a0 = fmaf(v, x.x, a0);
        a1 = fmaf(v, x.y, a1);
    }
    if (relu) { a0 = fmaxf(a0, 0.f); a1 = fmaxf(a1, 0.f); }
    reinterpret_cast<float2*>(out)[t] = make_float2(a0, a1);
}

// ======== smem-tiled SpMM: block = (batch b, 64-col tile dt) =============
// smem layout (bytes): Xs[255*64 f32]=65280 | cols=10200 | vals=10200 | rptr=1024
#define SPMM_SMEM 86720

__device__ __forceinline__ void spmm_stage(char* sm, int mat, const float* Zb,
                                           int d, int dt, int vw) {
    float* Xs   = reinterpret_cast<float*>(sm);
    int*   scol = reinterpret_cast<int*>(sm + 65280);
    float* sval = reinterpret_cast<float*>(sm + 75480);
    int*   srp  = reinterpret_cast<int*>(sm + 85680);
    const int tid = threadIdx.x;
    for (int e = tid; e < NNZ_E; e += 256) { scol[e] = g_cols[mat][e]; sval[e] = g_vals[mat][e]; }
    if (tid <= N_NODES) srp[tid] = g_rowptr[mat][tid];
    float4* X4 = reinterpret_cast<float4*>(Xs);
    if (vw < 64) {
        const float4 z = make_float4(0.f, 0.f, 0.f, 0.f);
        for (int i = tid; i < N_NODES * 16; i += 256) X4[i] = z;
    }
    __syncthreads();
    const int vw4 = vw >> 2;
    for (int it = tid; it < N_NODES * vw4; it += 256) {
        const int i = it / vw4;
        const int q = it - i * vw4;
        X4[i * 16 + q] = *reinterpret_cast<const float4*>(Zb + (size_t)i * d + dt + q * 4);
    }
    __syncthreads();
}

__device__ __forceinline__ float4 spmm_gather(const char* sm, int i, int q, int relu) {
    const float4* X4  = reinterpret_cast<const float4*>(sm);
    const int*  scol  = reinterpret_cast<const int*>(sm + 65280);
    const float* sval = reinterpret_cast<const float*>(sm + 75480);
    const int*  srp   = reinterpret_cast<const int*>(sm + 85680);
    const int p0 = srp[i], p1 = srp[i + 1];
    float4 acc = make_float4(0.f, 0.f, 0.f, 0.f);
    for (int e = p0; e < p1; e++) {
        const float v = sval[e];
        const float4 x = X4[scol[e] * 16 + q];
        acc.x = fmaf(v, x.x, acc.x);
        acc.y = fmaf(v, x.y, acc.y);
        acc.z = fmaf(v, x.z, acc.z);
        acc.w = fmaf(v, x.w, acc.w);
    }
    if (relu) {
        acc.x = fmaxf(acc.x, 0.f); acc.y = fmaxf(acc.y, 0.f);
        acc.z = fmaxf(acc.z, 0.f); acc.w = fmaxf(acc.w, 0.f);
    }
    return acc;
}

__device__ __forceinline__ void split_store(__nv_bfloat16* hi, __nv_bfloat16* lo,
                                            size_t off, float x) {
    const __nv_bfloat16 h = __float2bfloat16_rn(x);
    hi[off] = h;
    lo[off] = __float2bfloat16_rn(x - __bfloat162float(h));
}

// hilo variant: writes [M x Kpad] hi/lo bf16, zero-padding cols >= d
__global__ void __launch_bounds__(256)
spmm_tiled_hilo_kernel(int mat, const float* __restrict__ Z,
                       __nv_bfloat16* __restrict__ hi, __nv_bfloat16* __restrict__ lo,
                       int d, int Kpad, int relu) {
    extern __shared__ __align__(16) char sm[];
    const int b = blockIdx.x;
    const int dt = blockIdx.y * 64;
    int vw = d - dt;
    vw = vw < 0 ? 0 : (vw > 64 ? 64 : vw);
    spmm_stage(sm, mat, Z + (size_t)b * N_NODES * d, d, dt, vw);

    for (int it = threadIdx.x; it < N_NODES * 16; it += 256) {
        const int i = it >> 4;
        const int q = it & 15;
        const float4 a = spmm_gather(sm, i, q, relu);
        const size_t ob = ((size_t)b * N_NODES + i) * Kpad + dt + q * 4;
        __nv_bfloat16 h[4], l[4];
        {
            const float v[4] = { a.x, a.y, a.z, a.w };
#pragma unroll
            for (int j = 0; j < 4; j++) {
                h[j] = __float2bfloat16_rn(v[j]);
                l[j] = __float2bfloat16_rn(v[j] - __bfloat162float(h[j]));
            }
        }
        *reinterpret_cast<uint2*>(hi + ob) = *reinterpret_cast<uint2*>(h);
        *reinterpret_cast<uint2*>(lo + ob) = *reinterpret_cast<uint2*>(l);
    }
}

// fp32 variant: writes [M x d] fp32
__global__ void __launch_bounds__(256)
spmm_tiled_f32_kernel(int mat, const float* __restrict__ Z,
                      float* __restrict__ out, int d, int relu) {
    extern __shared__ __align__(16) char sm[];
    const int b = blockIdx.x;
    const int dt = blockIdx.y * 64;
    int vw = d - dt;
    vw = vw < 0 ? 0 : (vw > 64 ? 64 : vw);
    spmm_stage(sm, mat, Z + (size_t)b * N_NODES * d, d, dt, vw);

    const int vw4 = vw >> 2;
    for (int it = threadIdx.x; it < N_NODES * vw4; it += 256) {
        const int i = it / vw4;
        const int q = it - i * vw4;
        const float4 a = spmm_gather(sm, i, q, relu);
        *reinterpret_cast<float4*>(out + ((size_t)b * N_NODES + i) * d + dt + q * 4) = a;
    }
}

// ---------------- enc0: relu(x0*W0 + x1*W1 + rowsum*b) -> hi/lo (Kpad=448)
__global__ void enc0_hilo_kernel(const float* __restrict__ X2, const float* __restrict__ W,
                                 const float* __restrict__ b,
                                 __nv_bfloat16* __restrict__ hi, __nv_bfloat16* __restrict__ lo) {
    const int idx = blockIdx.x * blockDim.x + threadIdx.x;  // M_ROWS * 112 float4-groups
    if (idx >= M_ROWS * 112) return;
    const int m = idx / 112;
    const int q = idx - m * 112;
    const size_t obase = (size_t)m * MAXKPAD + q * 4;
    if (q >= 100) {
        const __nv_bfloat16 z = __float2bfloat16_rn(0.f);
#pragma unroll
        for (int j = 0; j < 4; j++) { hi[obase + j] = z; lo[obase + j] = z; }
        return;
    }
    const float2 a = reinterpret_cast<const float2*>(X2)[m];
    const float4 w0 = reinterpret_cast<const float4*>(W)[q];
    const float4 w1 = reinterpret_cast<const float4*>(W + 400)[q];
    const float4 bv = reinterpret_cast<const float4*>(b)[q];
    const float sc = g_rowsum[0][m % N_NODES];
    float o[4];
    o[0] = fmaxf(fmaf(a.x, w0.x, fmaf(a.y, w1.x, sc * bv.x)), 0.f);
    o[1] = fmaxf(fmaf(a.x, w0.y, fmaf(a.y, w1.y, sc * bv.y)), 0.f);
    o[2] = fmaxf(fmaf(a.x, w0.z, fmaf(a.y, w1.z, sc * bv.z)), 0.f);
    o[3] = fmaxf(fmaf(a.x, w0.w, fmaf(a.y, w1.w, sc * bv.w)), 0.f);
#pragma unroll
    for (int j = 0; j < 4; j++) split_store(hi, lo, obase + j, o[j]);
}

// ---------------- weight prep: W[K,N] fp32 -> Wstack[Npad, 3*Kpad] bf16 --
__global__ void prep_w_kernel(const float* __restrict__ W, int K, int N, int Kpad, int Npad) {
    const int t = blockIdx.x * blockDim.x + threadIdx.x;
    const int total = Npad * 3 * Kpad;
    if (t >= total) return;
    const int n = t / (3 * Kpad);
    const int kk = t - n * 3 * Kpad;
    const int seg = kk / Kpad;
    const int k = kk - seg * Kpad;
    float v = 0.f;
    if (n < N && k < K) v = W[(size_t)k * N + n];
    const __nv_bfloat16 h = __float2bfloat16_rn(v);
    g_wstack[t] = (seg == 1) ? __float2bfloat16_rn(v - __bfloat162float(h)) : h;
}

// ---------------- mma.sync bf16 GEMM (3-term fp32 emulation) -------------
// CTA 128x128, BK=64, cp.async double-buffered, 256 thr (warps 4x2).
#define GSTRIDE 144                       // bytes per smem row (128 + 16 pad)
#define GEMM_SMEM (4 * 128 * GSTRIDE)     // 73728: A0 B0 A1 B1

__global__ void __launch_bounds__(256, 2)
gemm_mma_kernel(const __nv_bfloat16* __restrict__ Ahi, const __nv_bfloat16* __restrict__ Alo,
                const __nv_bfloat16* __restrict__ Wst, const float* __restrict__ bias,
                int mat, int mode, float* __restrict__ C, int Kpad, int N) {
    extern __shared__ __align__(128) char gsm[];
    const uint32_t sbase = smem_u32(gsm);
    const uint32_t smA[2] = { sbase,             sbase + 2 * 128 * GSTRIDE };
    const uint32_t smB[2] = { sbase + 128 * GSTRIDE, sbase + 3 * 128 * GSTRIDE };

    const int tid = threadIdx.x;
    const int lane = tid & 31;
    const int w = tid >> 5;
    const int warpM = (w & 3) * 32;
    const int warpN = (w >> 2) * 64;
    const int mBase = blockIdx.x * 128;
    const int nBase = blockIdx.y * 128;

    float acc[2][8][4];
#pragma unroll
    for (int i = 0; i < 2; i++)
#pragma unroll
        for (int j = 0; j < 8; j++)
#pragma unroll
            for (int q = 0; q < 4; q++) acc[i][j][q] = 0.f;

    // ldmatrix per-lane byte offsets
    const int arow = (lane & 7) + ((lane >> 3) & 1) * 8;
    const int acol = (lane >> 4) * 8;
    uint32_t aoff[2];
#pragma unroll
    for (int mt = 0; mt < 2; mt++)
        aoff[mt] = (uint32_t)((warpM + mt * 16 + arow) * GSTRIDE + acol * 2);
    const int bn = (lane >> 4) * 8 + (lane & 7);
    const int bk = ((lane >> 3) & 1) * 8;
    uint32_t boff[4];
#pragma unroll
    for (int j = 0; j < 4; j++)
        boff[j] = (uint32_t)((warpN + j * 16 + bn) * GSTRIDE + bk * 2);

    // cp.async staging: thread t -> row t>>1, 64B half (t&1)
    const int r = tid >> 1;
    const int seg = tid & 1;
    const uint32_t stoff = (uint32_t)(r * GSTRIDE + seg * 64);
    const int wrow = 3 * Kpad;
    const int nch = Kpad >> 6;
    const int total = 3 * nch;

    auto issue = [&](int c, int buf) {
        const int phase = c / nch;
        const int kc = c - phase * nch;
        const __nv_bfloat16* Ap = (phase == 2 ? Alo : Ahi) +
                                  (size_t)(mBase + r) * Kpad + kc * 64 + seg * 32;
        const __nv_bfloat16* Bp = Wst + (size_t)(nBase + r) * wrow + phase * Kpad +
                                  kc * 64 + seg * 32;
#pragma unroll
        for (int q = 0; q < 4; q++) {
            cpasync16(smA[buf] + stoff + q * 16, Ap + q * 8);
            cpasync16(smB[buf] + stoff + q * 16, Bp + q * 8);
        }
        cp_commit();
    };

    issue(0, 0);
    for (int c = 0; c < total; c++) {
        const int buf = c & 1;
        if (c + 1 < total) {
            issue(c + 1, buf ^ 1);
            asm volatile("cp.async.wait_group 1;" ::: "memory");
        } else {
            asm volatile("cp.async.wait_group 0;" ::: "memory");
        }
        __syncthreads();

#pragma unroll
        for (int ks = 0; ks < 4; ks++) {
            uint32_t af[2][4];
#pragma unroll
            for (int mt = 0; mt < 2; mt++)
                ldmx4(af[mt][0], af[mt][1], af[mt][2], af[mt][3],
                      smA[buf] + aoff[mt] + ks * 32);
            uint32_t bf[8][2];
#pragma unroll
            for (int j = 0; j < 4; j++) {
                uint32_t r0, r1, r2, r3;
                ldmx4(r0, r1, r2, r3, smB[buf] + boff[j] + ks * 32);
                bf[2 * j][0] = r0;     bf[2 * j][1] = r1;
                bf[2 * j + 1][0] = r2; bf[2 * j + 1][1] = r3;
            }
#pragma unroll
            for (int mt = 0; mt < 2; mt++)
#pragma unroll
                for (int nt = 0; nt < 8; nt++)
                    mma16816(acc[mt][nt], af[mt], bf[nt]);
        }
        __syncthreads();
    }

    // epilogue
#pragma unroll
    for (int mt = 0; mt < 2; mt++) {
        const int r0 = mBase + warpM + mt * 16 + (lane >> 2);
        const int r1 = r0 + 8;
        const float s0 = (mode == 1) ? g_rowsum[mat][r0 % N_NODES] : 1.f;
        const float s1 = (mode == 1) ? g_rowsum[mat][r1 % N_NODES] : 1.f;
#pragma unroll
        for (int nt = 0; nt < 8; nt++) {
            const int n = nBase + warpN + nt * 8 + (lane & 3) * 2;
            if (n >= N) continue;
            const float b0 = bias[n], b1 = bias[n + 1];
            float o0 = acc[mt][nt][0] + b0 * s0;
            float o1 = acc[mt][nt][1] + b1 * s0;
            float o2 = acc[mt][nt][2] + b0 * s1;
            float o3 = acc[mt][nt][3] + b1 * s1;
            if (mode == 1) {
                o0 = fmaxf(o0, 0.f); o1 = fmaxf(o1, 0.f);
                o2 = fmaxf(o2, 0.f); o3 = fmaxf(o3, 0.f);
            }
            *reinterpret_cast<float2*>(C + (size_t)r0 * N + n) = make_float2(o0, o1);
            *reinterpret_cast<float2*>(C + (size_t)r1 * N + n) = make_float2(o2, o3);
        }
    }
}

// ---------------- thin GEMM for N=2 (dec2): warp per row -----------------
__global__ void gemm_thin_kernel(const float* __restrict__ X, const float* __restrict__ Wt,
                                 const float* __restrict__ bias, float* __restrict__ out, int K) {
    __shared__ float Ws[2 * MAXD];
    for (int i = threadIdx.x; i < 2 * K; i += blockDim.x) Ws[i] = Wt[i];
    __syncthreads();
    const int warp = threadIdx.x >> 5, lane = threadIdx.x & 31;
    const int row = blockIdx.x * 8 + warp;
    if (row >= M_ROWS) return;
    const float* x = X + (size_t)row * K;
    float a0 = 0.f, a1 = 0.f;
    for (int k = lane; k < K; k += 32) {
        const float xv = x[k];
        a0 = fmaf(xv, Ws[2 * k], a0);
        a1 = fmaf(xv, Ws[2 * k + 1], a1);
    }
#pragma unroll
    for (int off = 16; off; off >>= 1) {
        a0 += __shfl_down_sync(0xffffffffu, a0, off);
        a1 += __shfl_down_sync(0xffffffffu, a1, off);
    }
    if (lane == 0) {
        out[2 * row]     = a0 + bias[0];
        out[2 * row + 1] = a1 + bias[1];
    }
}

// ---------------- launch -------------------------------------------------
extern "C" void kernel_launch(void* const* d_in, const int* in_sizes, int n_in,
                              void* d_out, int out_size) {
    const float* H   = (const float*)d_in[0];
    const float* smv = (const float*)d_in[1];
    const float* spv = (const float*)d_in[2];
    const float* W[6];
    const float* bb[6];
    for (int i = 0; i < 6; i++) {
        W[i]  = (const float*)d_in[3 + 2 * i];
        bb[i] = (const float*)d_in[4 + 2 * i];
    }
    const int* smi = (const int*)d_in[15];
    const int* spi = (const int*)d_in[16];
    float* out = (float*)d_out;

    float *bufA, *bufB;
    __nv_bfloat16 *hi, *lo, *wst;
    cudaGetSymbolAddress((void**)&bufA, g_bufA);
    cudaGetSymbolAddress((void**)&bufB, g_bufB);
    cudaGetSymbolAddress((void**)&hi, g_hi);
    cudaGetSymbolAddress((void**)&lo, g_lo);
    cudaGetSymbolAddress((void**)&wst, g_wstack);

    cudaFuncSetAttribute(gemm_mma_kernel, cudaFuncAttributeMaxDynamicSharedMemorySize, GEMM_SMEM);
    cudaFuncSetAttribute(spmm_tiled_hilo_kernel, cudaFuncAttributeMaxDynamicSharedMemorySize, SPMM_SMEM);
    cudaFuncSetAttribute(spmm_tiled_f32_kernel, cudaFuncAttributeMaxDynamicSharedMemorySize, SPMM_SMEM);

    const int tpb = 256;
    const int mblk = M_ROWS / 128;  // 1020

    build_csr_kernel<<<2, 256>>>(smi, smv, spi, spv);

    // enc0 (2->400): SpMM(sm) on d=2, fused layer -> hi/lo (Kpad=448)
    spmm_d2_kernel<<<(M_ROWS + tpb - 1) / tpb, tpb>>>(0, H, bufA, 0);
    enc0_hilo_kernel<<<(M_ROWS * 112 + tpb - 1) / tpb, tpb>>>(bufA, W[0], bb[0], hi, lo);

    // enc1 (400->300), Kpad=448, Npad=384
    prep_w_kernel<<<(384 * 3 * 448 + tpb - 1) / tpb, tpb>>>(W[1], 400, 300, 448, 384);
    gemm_mma_kernel<<<dim3(mblk, 3), 256, GEMM_SMEM>>>(hi, lo, wst, bb[1], 0, 0, bufB, 448, 300);
    spmm_tiled_hilo_kernel<<<dim3(BATCH, 5), 256, SPMM_SMEM>>>(0, bufB, hi, lo, 300, 320, 1);

    // enc2 (300->100), Kpad=320, Npad=128
    prep_w_kernel<<<(128 * 3 * 320 + tpb - 1) / tpb, tpb>>>(W[2], 300, 100, 320, 128);
    gemm_mma_kernel<<<dim3(mblk, 1), 256, GEMM_SMEM>>>(hi, lo, wst, bb[2], 0, 0, bufA, 320, 100);
    spmm_tiled_f32_kernel<<<dim3(BATCH, 2), 256, SPMM_SMEM>>>(0, bufA, bufB, 100, 1);

    // dec0 (100->300): SpMM(sp)-first -> hi/lo (Kpad=128); GEMM mode1
    spmm_tiled_hilo_kernel<<<dim3(BATCH, 2), 256, SPMM_SMEM>>>(1, bufB, hi, lo, 100, 128, 0);
    prep_w_kernel<<<(384 * 3 * 128 + tpb - 1) / tpb, tpb>>>(W[3], 100, 300, 128, 384);
    gemm_mma_kernel<<<dim3(mblk, 3), 256, GEMM_SMEM>>>(hi, lo, wst, bb[3], 1, 1, bufA, 128, 300);

    // dec1 (300->400): SpMM(sp)-first -> hi/lo (Kpad=320); GEMM mode1
    spmm_tiled_hilo_kernel<<<dim3(BATCH, 5), 256, SPMM_SMEM>>>(1, bufA, hi, lo, 300, 320, 0);
    prep_w_kernel<<<(512 * 3 * 320 + tpb - 1) / tpb, tpb>>>(W[4], 300, 400, 320, 512);
    gemm_mma_kernel<<<dim3(mblk, 4), 256, GEMM_SMEM>>>(hi, lo, wst, bb[4], 1, 1, bufB, 320, 400);

    // dec2 (400->2): thin GEMM+bias, then SpMM(sp)+ReLU on d=2 into d_out
    gemm_thin_kernel<<<M_ROWS / 8, 256>>>(bufB, W[5], bb[5], bufA, 400);
    spmm_d2_kernel<<<(M_ROWS + tpb - 1) / tpb, tpb>>>(1, bufA, out, 1);
}

// round 12
// speedup vs baseline: 1.0769x; 1.0769x over previous
#include <cuda_runtime.h>
#include <cuda_bf16.h>
#include <cstdint>

#define N_NODES 255
#define NNZ_E   2550
#define BATCH   512
#define M_ROWS  (BATCH * N_NODES)   // 130560 (divisible by 128)
#define MAXD    400
#define MAXKPAD 448

// ---------------- device scratch (no allocations allowed) ----------------
__device__ __align__(256) float         g_bufA[M_ROWS * MAXD];
__device__ __align__(256) float         g_bufB[M_ROWS * MAXD];
__device__ __align__(256) __nv_bfloat16 g_hi[M_ROWS * MAXKPAD];
__device__ __align__(256) __nv_bfloat16 g_lo[M_ROWS * MAXKPAD];
__device__ __align__(256) __nv_bfloat16 g_wstack[520192];   // max Npad*3*Kpad
__device__ int   g_rowptr[2][N_NODES + 1];
__device__ int   g_cols[2][NNZ_E];
__device__ float g_vals[2][NNZ_E];
__device__ float g_rowsum[2][N_NODES];

// ================= PTX helpers =================
__device__ __forceinline__ uint32_t smem_u32(const void* p) {
    uint32_t a;
    asm("{ .reg .u64 t; cvta.to.shared.u64 t, %1; cvt.u32.u64 %0, t; }" : "=r"(a) : "l"(p));
    return a;
}
__device__ __forceinline__ void ldmx4(uint32_t& r0, uint32_t& r1, uint32_t& r2, uint32_t& r3,
                                      uint32_t addr) {
    asm volatile("ldmatrix.sync.aligned.m8n8.x4.shared.b16 {%0,%1,%2,%3}, [%4];"
                 : "=r"(r0), "=r"(r1), "=r"(r2), "=r"(r3) : "r"(addr));
}
__device__ __forceinline__ void mma16816(float* d, const uint32_t* a, const uint32_t* b) {
    asm volatile(
        "mma.sync.aligned.m16n8k16.row.col.f32.bf16.bf16.f32 "
        "{%0,%1,%2,%3}, {%4,%5,%6,%7}, {%8,%9}, {%0,%1,%2,%3};"
        : "+f"(d[0]), "+f"(d[1]), "+f"(d[2]), "+f"(d[3])
        : "r"(a[0]), "r"(a[1]), "r"(a[2]), "r"(a[3]), "r"(b[0]), "r"(b[1]));
}
__device__ __forceinline__ void cpasync16(uint32_t dst, const void* src) {
    asm volatile("cp.async.cg.shared.global [%0], [%1], 16;" :: "r"(dst), "l"(src) : "memory");
}
__device__ __forceinline__ void cp_commit() {
    asm volatile("cp.async.commit_group;" ::: "memory");
}

// ---------------- deterministic COO -> CSR build (1 block per matrix) ----
__global__ void build_csr_kernel(const int* __restrict__ sm_idx, const float* __restrict__ sm_val,
                                 const int* __restrict__ sp_idx, const float* __restrict__ sp_val) {
    __shared__ int   srow[NNZ_E];
    __shared__ int   scolg[NNZ_E];
    __shared__ float sval[NNZ_E];
    __shared__ int   rptr[N_NODES + 1];
    __shared__ int   cnt[N_NODES];
    const int mat = blockIdx.x;
    const int*   idx = mat ? sp_idx : sm_idx;
    const float* val = mat ? sp_val : sm_val;
    const int t = threadIdx.x;

    for (int e = t; e < NNZ_E; e += blockDim.x) {
        srow[e]  = idx[2 * e];
        scolg[e] = idx[2 * e + 1];
        sval[e]  = val[e];
    }
    for (int i = t; i < N_NODES; i += blockDim.x) cnt[i] = 0;
    __syncthreads();
    for (int e = t; e < NNZ_E; e += blockDim.x) atomicAdd(&cnt[srow[e]], 1);
    __syncthreads();
    if (t == 0) {
        int s = 0;
        for (int i = 0; i < N_NODES; i++) { rptr[i] = s; s += cnt[i]; }
        rptr[N_NODES] = s;
    }
    __syncthreads();
    // row-parallel deterministic fill: thread per row scans edges in order
    for (int i = t; i < N_NODES; i += blockDim.x) {
        int c = 0;
        float s = 0.f;
        const int base = rptr[i];
        for (int e = 0; e < NNZ_E; e++) {
            if (srow[e] == i) {
                g_cols[mat][base + c] = scolg[e];
                g_vals[mat][base + c] = sval[e];
                c++;
                s += sval[e];
            }
        }
        g_rowsum[mat][i] = s;
    }
    for (int i = t; i <= N_NODES; i += blockDim.x) g_rowptr[mat][i] = rptr[i];
}

// ---------------- SpMM, feature dim = 2 ----------------------------------
__global__ void spmm_d2_kernel(int mat, const float* __restrict__ X,
                               float* __restrict__ out, int relu) {
    const int t = blockIdx.x * blockDim.x + threadIdx.x;
    if (t >= M_ROWS) return;
    const int b = t / N_NODES;
    const int i = t - b * N_NODES;
    const int p0 = g_rowptr[mat][i], p1 = g_rowptr[mat][i + 1];
    const float2* Xb = reinterpret_cast<const float2*>(X) + (size_t)b * N_NODES;
    float a0 = 0.f, a1 = 0.f;
    for (int e = p0; e < p1; e++) {
        const float v = g_vals[mat][e];
        const float2 x = Xb[g_cols[mat][e]];
        a0 = fmaf(v, x.x, a0);
        a1 = fmaf(v, x.y, a1);
    }
    if (relu) { a0 = fmaxf(a0, 0.f); a1 = fmaxf(a1, 0.f); }
    reinterpret_cast<float2*>(out)[t] = make_float2(a0, a1);
}

// ======== per-batch smem SpMM: block = batch b, inner loop over 64-col tiles
// smem bytes: Xs 65280 | scol 10200 | sval 10200 | rptr 1028  -> 86720
#define SPMM_SMEM 86720
#define SM_XS   0
#define SM_COL  65280
#define SM_VAL  75480
#define SM_RP   85680

__device__ __forceinline__ void spmm_stage_csr(char* sm, int mat) {
    int*   scol = reinterpret_cast<int*>(sm + SM_COL);
    float* sval = reinterpret_cast<float*>(sm + SM_VAL);
    int*   srp  = reinterpret_cast<int*>(sm + SM_RP);
    const int tid = threadIdx.x;
    for (int e = tid; e < NNZ_E; e += 256) { scol[e] = g_cols[mat][e]; sval[e] = g_vals[mat][e]; }
    if (tid <= N_NODES) srp[tid] = g_rowptr[mat][tid];
}

__device__ __forceinline__ void spmm_stage_x(char* sm, const float* Zb, int d, int dt, int vw) {
    float4* X4 = reinterpret_cast<float4*>(sm + SM_XS);
    const int tid = threadIdx.x;
    const int vw4 = vw >> 2;
    if (vw4 < 16) {  // zero only the pad columns (disjoint from staged region)
        const int pw = 16 - vw4;
        const float4 z = make_float4(0.f, 0.f, 0.f, 0.f);
        for (int it = tid; it < N_NODES * pw; it += 256) {
            const int i = it / pw;
            const int q = vw4 + (it - i * pw);
            X4[i * 16 + q] = z;
        }
    }
    for (int it = tid; it < N_NODES * vw4; it += 256) {
        const int i = it / vw4;
        const int q = it - i * vw4;
        X4[i * 16 + q] = *reinterpret_cast<const float4*>(Zb + (size_t)i * d + dt + q * 4);
    }
}

__device__ __forceinline__ float4 spmm_gather(const char* sm, int i, int q, int relu) {
    const float4* X4  = reinterpret_cast<const float4*>(sm + SM_XS);
    const int*  scol  = reinterpret_cast<const int*>(sm + SM_COL);
    const float* sval = reinterpret_cast<const float*>(sm + SM_VAL);
    const int*  srp   = reinterpret_cast<const int*>(sm + SM_RP);
    const int p0 = srp[i], p1 = srp[i + 1];
    float4 acc = make_float4(0.f, 0.f, 0.f, 0.f);
    for (int e = p0; e < p1; e++) {
        const float v = sval[e];
        const float4 x = X4[scol[e] * 16 + q];
        acc.x = fmaf(v, x.x, acc.x);
        acc.y = fmaf(v, x.y, acc.y);
        acc.z = fmaf(v, x.z, acc.z);
        acc.w = fmaf(v, x.w, acc.w);
    }
    if (relu) {
        acc.x = fmaxf(acc.x, 0.f); acc.y = fmaxf(acc.y, 0.f);
        acc.z = fmaxf(acc.z, 0.f); acc.w = fmaxf(acc.w, 0.f);
    }
    return acc;
}

// hilo variant: writes [M x Kpad] hi/lo bf16 (Kpad multiple of 64)
__global__ void __launch_bounds__(256)
spmm_batch_hilo_kernel(int mat, const float* __restrict__ Z,
                       __nv_bfloat16* __restrict__ hi, __nv_bfloat16* __restrict__ lo,
                       int d, int Kpad, int relu) {
    extern __shared__ __align__(16) char sm[];
    const int b = blockIdx.x;
    const float* Zb = Z + (size_t)b * N_NODES * d;
    spmm_stage_csr(sm, mat);
    const int ntile = Kpad >> 6;
    for (int t = 0; t < ntile; t++) {
        const int dt = t * 64;
        int vw = d - dt;
        vw = vw < 0 ? 0 : (vw > 64 ? 64 : vw);
        if (t > 0) __syncthreads();       // previous gather done before Xs overwrite
        spmm_stage_x(sm, Zb, d, dt, vw);
        __syncthreads();
        for (int it = threadIdx.x; it < N_NODES * 16; it += 256) {
            const int i = it >> 4;
            const int q = it & 15;
            const float4 a = spmm_gather(sm, i, q, relu);
            const size_t ob = ((size_t)b * N_NODES + i) * Kpad + dt + q * 4;
            __nv_bfloat16 h[4], l[4];
            const float v[4] = { a.x, a.y, a.z, a.w };
#pragma unroll
            for (int j = 0; j < 4; j++) {
                h[j] = __float2bfloat16_rn(v[j]);
                l[j] = __float2bfloat16_rn(v[j] - __bfloat162float(h[j]));
            }
            *reinterpret_cast<uint2*>(hi + ob) = *reinterpret_cast<uint2*>(h);
            *reinterpret_cast<uint2*>(lo + ob) = *reinterpret_cast<uint2*>(l);
        }
    }
}

// fp32 variant: writes [M x d] fp32
__global__ void __launch_bounds__(256)
spmm_batch_f32_kernel(int mat, const float* __restrict__ Z,
                      float* __restrict__ out, int d, int relu) {
    extern __shared__ __align__(16) char sm[];
    const int b = blockIdx.x;
    const float* Zb = Z + (size_t)b * N_NODES * d;
    spmm_stage_csr(sm, mat);
    const int ntile = (d + 63) >> 6;
    for (int t = 0; t < ntile; t++) {
        const int dt = t * 64;
        int vw = d - dt;
        vw = vw > 64 ? 64 : vw;
        if (t > 0) __syncthreads();
        spmm_stage_x(sm, Zb, d, dt, vw);
        __syncthreads();
        const int vw4 = vw >> 2;
        for (int it = threadIdx.x; it < N_NODES * vw4; it += 256) {
            const int i = it / vw4;
            const int q = it - i * vw4;
            const float4 a = spmm_gather(sm, i, q, relu);
            *reinterpret_cast<float4*>(out + ((size_t)b * N_NODES + i) * d + dt + q * 4) = a;
        }
    }
}

// ---------------- enc0: relu(x0*W0 + x1*W1 + rowsum*b) -> hi/lo (Kpad=448)
__device__ __forceinline__ void split_store(__nv_bfloat16* hi, __nv_bfloat16* lo,
                                            size_t off, float x) {
    const __nv_bfloat16 h = __float2bfloat16_rn(x);
    hi[off] = h;
    lo[off] = __float2bfloat16_rn(x - __bfloat162float(h));
}
__global__ void enc0_hilo_kernel(const float* __restrict__ X2, const float* __restrict__ W,
                                 const float* __restrict__ b,
                                 __nv_bfloat16* __restrict__ hi, __nv_bfloat16* __restrict__ lo) {
    const int idx = blockIdx.x * blockDim.x + threadIdx.x;  // M_ROWS * 112 float4-groups
    if (idx >= M_ROWS * 112) return;
    const int m = idx / 112;
    const int q = idx - m * 112;
    const size_t obase = (size_t)m * MAXKPAD + q * 4;
    if (q >= 100) {
        const __nv_bfloat16 z = __float2bfloat16_rn(0.f);
#pragma unroll
        for (int j = 0; j < 4; j++) { hi[obase + j] = z; lo[obase + j] = z; }
        return;
    }
    const float2 a = reinterpret_cast<const float2*>(X2)[m];
    const float4 w0 = reinterpret_cast<const float4*>(W)[q];
    const float4 w1 = reinterpret_cast<const float4*>(W + 400)[q];
    const float4 bv = reinterpret_cast<const float4*>(b)[q];
    const float sc = g_rowsum[0][m % N_NODES];
    float o[4];
    o[0] = fmaxf(fmaf(a.x, w0.x, fmaf(a.y, w1.x, sc * bv.x)), 0.f);
    o[1] = fmaxf(fmaf(a.x, w0.y, fmaf(a.y, w1.y, sc * bv.y)), 0.f);
    o[2] = fmaxf(fmaf(a.x, w0.z, fmaf(a.y, w1.z, sc * bv.z)), 0.f);
    o[3] = fmaxf(fmaf(a.x, w0.w, fmaf(a.y, w1.w, sc * bv.w)), 0.f);
#pragma unroll
    for (int j = 0; j < 4; j++) split_store(hi, lo, obase + j, o[j]);
}

// ---------------- weight prep: W[K,N] fp32 -> Wstack[Npad, 3*Kpad] bf16 --
__global__ void prep_w_kernel(const float* __restrict__ W, int K, int N, int Kpad, int Npad) {
    const int t = blockIdx.x * blockDim.x + threadIdx.x;
    const int total = Npad * 3 * Kpad;
    if (t >= total) return;
    const int n = t / (3 * Kpad);
    const int kk = t - n * 3 * Kpad;
    const int seg = kk / Kpad;
    const int k = kk - seg * Kpad;
    float v = 0.f;
    if (n < N && k < K) v = W[(size_t)k * N + n];
    const __nv_bfloat16 h = __float2bfloat16_rn(v);
    g_wstack[t] = (seg == 1) ? __float2bfloat16_rn(v - __bfloat162float(h)) : h;
}

// ---------------- mma.sync bf16 GEMM (3-term fp32 emulation) -------------
// R8 layout (CTA 128x128, BK=32, ASTRIDE=80, warps 4x2 -> 32x64) with a
// 3-stage cp.async pipeline: one __syncthreads per chunk, loads 2 ahead.
#define ASTRIDE 80                          // bytes per smem row (64 + 16 pad)
#define GSTAGE  (2 * 128 * ASTRIDE)         // 20480: A tile + B tile
#define GEMM_SMEM (3 * GSTAGE)              // 61440

__global__ void __launch_bounds__(256, 2)
gemm_mma_kernel(const __nv_bfloat16* __restrict__ Ahi, const __nv_bfloat16* __restrict__ Alo,
                const __nv_bfloat16* __restrict__ Wst, const float* __restrict__ bias,
                int mat, int mode, float* __restrict__ C, int Kpad, int N) {
    extern __shared__ __align__(128) char gsm[];
    const uint32_t sbase = smem_u32(gsm);
    uint32_t smA[3], smB[3];
#pragma unroll
    for (int s = 0; s < 3; s++) {
        smA[s] = sbase + s * GSTAGE;
        smB[s] = sbase + s * GSTAGE + 128 * ASTRIDE;
    }

    const int tid = threadIdx.x;
    const int lane = tid & 31;
    const int w = tid >> 5;
    const int warpM = (w & 3) * 32;
    const int warpN = (w >> 2) * 64;
    const int mBase = blockIdx.x * 128;
    const int nBase = blockIdx.y * 128;

    float acc[2][8][4];
#pragma unroll
    for (int i = 0; i < 2; i++)
#pragma unroll
        for (int j = 0; j < 8; j++)
#pragma unroll
            for (int q = 0; q < 4; q++) acc[i][j][q] = 0.f;

    // ldmatrix per-lane byte offsets
    const int arow = (lane & 7) + ((lane >> 3) & 1) * 8;
    const int acol = (lane >> 4) * 8;
    uint32_t aoff[2];
#pragma unroll
    for (int mt = 0; mt < 2; mt++)
        aoff[mt] = (uint32_t)((warpM + mt * 16 + arow) * ASTRIDE + acol * 2);
    const int bn = (lane >> 4) * 8 + (lane & 7);
    const int bk = ((lane >> 3) & 1) * 8;
    uint32_t boff[4];
#pragma unroll
    for (int j = 0; j < 4; j++)
        boff[j] = (uint32_t)((warpN + j * 16 + bn) * ASTRIDE + bk * 2);

    // cp.async staging: thread -> row tid>>1, 32B half (tid&1)
    const int ldrow = tid >> 1;
    const int ch0 = (tid & 1) * 2;
    const uint32_t stoff = (uint32_t)(ldrow * ASTRIDE + ch0 * 16);
    const int wrow = 3 * Kpad;
    const int nch = Kpad >> 5;
    const int total = 3 * nch;
    const __nv_bfloat16* BrowBase = Wst + (size_t)(nBase + ldrow) * wrow;

    auto issue = [&](int c, int st) {
        const int phase = c / nch;
        const int kc = c - phase * nch;
        const __nv_bfloat16* Ap = (phase == 2 ? Alo : Ahi) +
                                  (size_t)(mBase + ldrow) * Kpad + kc * 32 + ch0 * 8;
        const __nv_bfloat16* Bp = BrowBase + phase * Kpad + kc * 32 + ch0 * 8;
        cpasync16(smA[st] + stoff, Ap);
        cpasync16(smA[st] + stoff + 16, Ap + 8);
        cpasync16(smB[st] + stoff, Bp);
        cpasync16(smB[st] + stoff + 16, Bp + 8);
        cp_commit();
    };

    issue(0, 0);
    issue(1, 1);

    int st = 0, stNext = 2;
    for (int c = 0; c < total; c++) {
        if (c == total - 1) {
            asm volatile("cp.async.wait_group 0;" ::: "memory");
        } else {
            asm volatile("cp.async.wait_group 1;" ::: "memory");
        }
        __syncthreads();
        if (c + 2 < total) issue(c + 2, stNext);

        // compute on stage st (BK=32 -> 2 k-steps)
#pragma unroll
        for (int ks = 0; ks < 2; ks++) {
            uint32_t af[2][4];
#pragma unroll
            for (int mt = 0; mt < 2; mt++)
                ldmx4(af[mt][0], af[mt][1], af[mt][2], af[mt][3],
                      smA[st] + aoff[mt] + ks * 32);
            uint32_t bf[8][2];
#pragma unroll
            for (int j = 0; j < 4; j++) {
                uint32_t r0, r1, r2, r3;
                ldmx4(r0, r1, r2, r3, smB[st] + boff[j] + ks * 32);
                bf[2 * j][0] = r0;     bf[2 * j][1] = r1;
                bf[2 * j + 1][0] = r2; bf[2 * j + 1][1] = r3;
            }
#pragma unroll
            for (int mt = 0; mt < 2; mt++)
#pragma unroll
                for (int nt = 0; nt < 8; nt++)
                    mma16816(acc[mt][nt], af[mt], bf[nt]);
        }

        st = (st == 2) ? 0 : st + 1;
        stNext = (stNext == 2) ? 0 : stNext + 1;
    }

    // epilogue
#pragma unroll
    for (int mt = 0; mt < 2; mt++) {
        const int r0 = mBase + warpM + mt * 16 + (lane >> 2);
        const int r1 = r0 + 8;
        const float s0 = (mode == 1) ? g_rowsum[mat][r0 % N_NODES] : 1.f;
        const float s1 = (mode == 1) ? g_rowsum[mat][r1 % N_NODES] : 1.f;
#pragma unroll
        for (int nt = 0; nt < 8; nt++) {
            const int n = nBase + warpN + nt * 8 + (lane & 3) * 2;
            if (n >= N) continue;
            const float b0 = bias[n], b1 = bias[n + 1];
            float o0 = acc[mt][nt][0] + b0 * s0;
            float o1 = acc[mt][nt][1] + b1 * s0;
            float o2 = acc[mt][nt][2] + b0 * s1;
            float o3 = acc[mt][nt][3] + b1 * s1;
            if (mode == 1) {
                o0 = fmaxf(o0, 0.f); o1 = fmaxf(o1, 0.f);
                o2 = fmaxf(o2, 0.f); o3 = fmaxf(o3, 0.f);
            }
            *reinterpret_cast<float2*>(C + (size_t)r0 * N + n) = make_float2(o0, o1);
            *reinterpret_cast<float2*>(C + (size_t)r1 * N + n) = make_float2(o2, o3);
        }
    }
}

// ---------------- thin GEMM for N=2 (dec2): warp per row -----------------
__global__ void gemm_thin_kernel(const float* __restrict__ X, const float* __restrict__ Wt,
                                 const float* __restrict__ bias, float* __restrict__ out, int K) {
    __shared__ float Ws[2 * MAXD];
    for (int i = threadIdx.x; i < 2 * K; i += blockDim.x) Ws[i] = Wt[i];
    __syncthreads();
    const int warp = threadIdx.x >> 5, lane = threadIdx.x & 31;
    const int row = blockIdx.x * 8 + warp;
    if (row >= M_ROWS) return;
    const float* x = X + (size_t)row * K;
    float a0 = 0.f, a1 = 0.f;
    for (int k = lane; k < K; k += 32) {
        const float xv = x[k];
        a0 = fmaf(xv, Ws[2 * k], a0);
        a1 = fmaf(xv, Ws[2 * k + 1], a1);
    }
#pragma unroll
    for (int off = 16; off; off >>= 1) {
        a0 += __shfl_down_sync(0xffffffffu, a0, off);
        a1 += __shfl_down_sync(0xffffffffu, a1, off);
    }
    if (lane == 0) {
        out[2 * row]     = a0 + bias[0];
        out[2 * row + 1] = a1 + bias[1];
    }
}

// ---------------- launch -------------------------------------------------
extern "C" void kernel_launch(void* const* d_in, const int* in_sizes, int n_in,
                              void* d_out, int out_size) {
    const float* H   = (const float*)d_in[0];
    const float* smv = (const float*)d_in[1];
    const float* spv = (const float*)d_in[2];
    const float* W[6];
    const float* bb[6];
    for (int i = 0; i < 6; i++) {
        W[i]  = (const float*)d_in[3 + 2 * i];
        bb[i] = (const float*)d_in[4 + 2 * i];
    }
    const int* smi = (const int*)d_in[15];
    const int* spi = (const int*)d_in[16];
    float* out = (float*)d_out;

    float *bufA, *bufB;
    __nv_bfloat16 *hi, *lo, *wst;
    cudaGetSymbolAddress((void**)&bufA, g_bufA);
    cudaGetSymbolAddress((void**)&bufB, g_bufB);
    cudaGetSymbolAddress((void**)&hi, g_hi);
    cudaGetSymbolAddress((void**)&lo, g_lo);
    cudaGetSymbolAddress((void**)&wst, g_wstack);

    cudaFuncSetAttribute(gemm_mma_kernel, cudaFuncAttributeMaxDynamicSharedMemorySize, GEMM_SMEM);
    cudaFuncSetAttribute(spmm_batch_hilo_kernel, cudaFuncAttributeMaxDynamicSharedMemorySize, SPMM_SMEM);
    cudaFuncSetAttribute(spmm_batch_f32_kernel, cudaFuncAttributeMaxDynamicSharedMemorySize, SPMM_SMEM);

    const int tpb = 256;
    const int mblk = M_ROWS / 128;  // 1020

    build_csr_kernel<<<2, 256>>>(smi, smv, spi, spv);

    // enc0 (2->400): SpMM(sm) on d=2, fused layer -> hi/lo (Kpad=448)
    spmm_d2_kernel<<<(M_ROWS + tpb - 1) / tpb, tpb>>>(0, H, bufA, 0);
    enc0_hilo_kernel<<<(M_ROWS * 112 + tpb - 1) / tpb, tpb>>>(bufA, W[0], bb[0], hi, lo);

    // enc1 (400->300), Kpad=448, Npad=384
    prep_w_kernel<<<(384 * 3 * 448 + tpb - 1) / tpb, tpb>>>(W[1], 400, 300, 448, 384);
    gemm_mma_kernel<<<dim3(mblk, 3), 256, GEMM_SMEM>>>(hi, lo, wst, bb[1], 0, 0, bufB, 448, 300);
    spmm_batch_hilo_kernel<<<BATCH, 256, SPMM_SMEM>>>(0, bufB, hi, lo, 300, 320, 1);

    // enc2 (300->100), Kpad=320, Npad=128
    prep_w_kernel<<<(128 * 3 * 320 + tpb - 1) / tpb, tpb>>>(W[2], 300, 100, 320, 128);
    gemm_mma_kernel<<<dim3(mblk, 1), 256, GEMM_SMEM>>>(hi, lo, wst, bb[2], 0, 0, bufA, 320, 100);
    spmm_batch_f32_kernel<<<BATCH, 256, SPMM_SMEM>>>(0, bufA, bufB, 100, 1);

    // dec0 (100->300): SpMM(sp)-first -> hi/lo (Kpad=128); GEMM mode1
    spmm_batch_hilo_kernel<<<BATCH, 256, SPMM_SMEM>>>(1, bufB, hi, lo, 100, 128, 0);
    prep_w_kernel<<<(384 * 3 * 128 + tpb - 1) / tpb, tpb>>>(W[3], 100, 300, 128, 384);
    gemm_mma_kernel<<<dim3(mblk, 3), 256, GEMM_SMEM>>>(hi, lo, wst, bb[3], 1, 1, bufA, 128, 300);

    // dec1 (300->400): SpMM(sp)-first -> hi/lo (Kpad=320); GEMM mode1
    spmm_batch_hilo_kernel<<<BATCH, 256, SPMM_SMEM>>>(1, bufA, hi, lo, 300, 320, 0);
    prep_w_kernel<<<(512 * 3 * 320 + tpb - 1) / tpb, tpb>>>(W[4], 300, 400, 320, 512);
    gemm_mma_kernel<<<dim3(mblk, 4), 256, GEMM_SMEM>>>(hi, lo, wst, bb[4], 1, 1, bufB, 320, 400);

    // dec2 (400->2): thin GEMM+bias, then SpMM(sp)+ReLU on d=2 into d_out
    gemm_thin_kernel<<<M_ROWS / 8, 256>>>(bufB, W[5], bb[5], bufA, 400);
    spmm_d2_kernel<<<(M_ROWS + tpb - 1) / tpb, tpb>>>(1, bufA, out, 1);
}

// round 13
// speedup vs baseline: 1.2942x; 1.2018x over previous
#include <cuda_runtime.h>
#include <cuda_bf16.h>
#include <cstdint>

#define N_NODES 255
#define NNZ_E   2550
#define BATCH   512
#define M_ROWS  (BATCH * N_NODES)   // 130560 (divisible by 128)
#define MAXD    400
#define MAXKPAD 448

// ---------------- device scratch (no allocations allowed) ----------------
__device__ __align__(256) float         g_bufA[M_ROWS * MAXD];
__device__ __align__(256) float         g_bufB[M_ROWS * MAXD];
__device__ __align__(256) __nv_bfloat16 g_hi[M_ROWS * MAXKPAD];
__device__ __align__(256) __nv_bfloat16 g_lo[M_ROWS * MAXKPAD];
__device__ __align__(256) __nv_bfloat16 g_wstack[520192];   // max Npad*2*Kpad = 344064
__device__ int   g_rowptr[2][N_NODES + 1];
__device__ int   g_cols[2][NNZ_E];
__device__ float g_vals[2][NNZ_E];
__device__ float g_rowsum[2][N_NODES];

// ================= PTX helpers =================
__device__ __forceinline__ uint32_t smem_u32(const void* p) {
    uint32_t a;
    asm("{ .reg .u64 t; cvta.to.shared.u64 t, %1; cvt.u32.u64 %0, t; }" : "=r"(a) : "l"(p));
    return a;
}
__device__ __forceinline__ void ldmx4(uint32_t& r0, uint32_t& r1, uint32_t& r2, uint32_t& r3,
                                      uint32_t addr) {
    asm volatile("ldmatrix.sync.aligned.m8n8.x4.shared.b16 {%0,%1,%2,%3}, [%4];"
                 : "=r"(r0), "=r"(r1), "=r"(r2), "=r"(r3) : "r"(addr));
}
__device__ __forceinline__ void mma16816(float* d, const uint32_t* a, uint32_t b0, uint32_t b1) {
    asm volatile(
        "mma.sync.aligned.m16n8k16.row.col.f32.bf16.bf16.f32 "
        "{%0,%1,%2,%3}, {%4,%5,%6,%7}, {%8,%9}, {%0,%1,%2,%3};"
        : "+f"(d[0]), "+f"(d[1]), "+f"(d[2]), "+f"(d[3])
        : "r"(a[0]), "r"(a[1]), "r"(a[2]), "r"(a[3]), "r"(b0), "r"(b1));
}
__device__ __forceinline__ void cpasync16(uint32_t dst, const void* src) {
    asm volatile("cp.async.cg.shared.global [%0], [%1], 16;" :: "r"(dst), "l"(src) : "memory");
}
__device__ __forceinline__ void cp_commit() {
    asm volatile("cp.async.commit_group;" ::: "memory");
}

// ---------------- deterministic COO -> CSR build (1 block per matrix) ----
__global__ void build_csr_kernel(const int* __restrict__ sm_idx, const float* __restrict__ sm_val,
                                 const int* __restrict__ sp_idx, const float* __restrict__ sp_val) {
    __shared__ int   srow[NNZ_E];
    __shared__ int   scolg[NNZ_E];
    __shared__ float sval[NNZ_E];
    __shared__ int   rptr[N_NODES + 1];
    __shared__ int   cnt[N_NODES];
    const int mat = blockIdx.x;
    const int*   idx = mat ? sp_idx : sm_idx;
    const float* val = mat ? sp_val : sm_val;
    const int t = threadIdx.x;

    for (int e = t; e < NNZ_E; e += blockDim.x) {
        srow[e]  = idx[2 * e];
        scolg[e] = idx[2 * e + 1];
        sval[e]  = val[e];
    }
    for (int i = t; i < N_NODES; i += blockDim.x) cnt[i] = 0;
    __syncthreads();
    for (int e = t; e < NNZ_E; e += blockDim.x) atomicAdd(&cnt[srow[e]], 1);
    __syncthreads();
    if (t == 0) {
        int s = 0;
        for (int i = 0; i < N_NODES; i++) { rptr[i] = s; s += cnt[i]; }
        rptr[N_NODES] = s;
    }
    __syncthreads();
    // row-parallel deterministic fill: thread per row scans edges in order
    for (int i = t; i < N_NODES; i += blockDim.x) {
        int c = 0;
        float s = 0.f;
        const int base = rptr[i];
        for (int e = 0; e < NNZ_E; e++) {
            if (srow[e] == i) {
                g_cols[mat][base + c] = scolg[e];
                g_vals[mat][base + c] = sval[e];
                c++;
                s += sval[e];
            }
        }
        g_rowsum[mat][i] = s;
    }
    for (int i = t; i <= N_NODES; i += blockDim.x) g_rowptr[mat][i] = rptr[i];
}

// ---------------- SpMM, feature dim = 2 ----------------------------------
__global__ void spmm_d2_kernel(int mat, const float* __restrict__ X,
                               float* __restrict__ out, int relu) {
    const int t = blockIdx.x * blockDim.x + threadIdx.x;
    if (t >= M_ROWS) return;
    const int b = t / N_NODES;
    const int i = t - b * N_NODES;
    const int p0 = g_rowptr[mat][i], p1 = g_rowptr[mat][i + 1];
    const float2* Xb = reinterpret_cast<const float2*>(X) + (size_t)b * N_NODES;
    float a0 = 0.f, a1 = 0.f;
    for (int e = p0; e < p1; e++) {
        const float v = g_vals[mat][e];
        const float2 x = Xb[g_cols[mat][e]];
        a0 = fmaf(v, x.x, a0);
        a1 = fmaf(v, x.y, a1);
    }
    if (relu) { a0 = fmaxf(a0, 0.f); a1 = fmaxf(a1, 0.f); }
    reinterpret_cast<float2*>(out)[t] = make_float2(a0, a1);
}

// ======== per-batch smem SpMM: block = batch b, inner loop over 64-col tiles
// Half-warp per row, lane = q: edge value/col reads are smem broadcasts.
// smem bytes: Xs 65280 | scol 10200 | sval 10200 | rptr 1028  -> 86720
#define SPMM_SMEM 86720
#define SM_XS   0
#define SM_COL  65280
#define SM_VAL  75480
#define SM_RP   85680

__device__ __forceinline__ void spmm_stage_csr(char* sm, int mat) {
    int*   scol = reinterpret_cast<int*>(sm + SM_COL);
    float* sval = reinterpret_cast<float*>(sm + SM_VAL);
    int*   srp  = reinterpret_cast<int*>(sm + SM_RP);
    const int tid = threadIdx.x;
    for (int e = tid; e < NNZ_E; e += 256) { scol[e] = g_cols[mat][e]; sval[e] = g_vals[mat][e]; }
    if (tid <= N_NODES) srp[tid] = g_rowptr[mat][tid];
}

__device__ __forceinline__ void spmm_stage_x(char* sm, const float* Zb, int d, int dt, int vw) {
    float4* X4 = reinterpret_cast<float4*>(sm + SM_XS);
    const int tid = threadIdx.x;
    const int vw4 = vw >> 2;
    if (vw4 < 16) {  // zero only the pad columns (disjoint from staged region)
        const int pw = 16 - vw4;
        const float4 z = make_float4(0.f, 0.f, 0.f, 0.f);
        for (int it = tid; it < N_NODES * pw; it += 256) {
            const int i = it / pw;
            const int q = vw4 + (it - i * pw);
            X4[i * 16 + q] = z;
        }
    }
    for (int it = tid; it < N_NODES * vw4; it += 256) {
        const int i = it / vw4;
        const int q = it - i * vw4;
        X4[i * 16 + q] = *reinterpret_cast<const float4*>(Zb + (size_t)i * d + dt + q * 4);
    }
}

// half-warp-per-row gather: i fixed per half-warp, q = lane&15
__device__ __forceinline__ float4 spmm_gather_row(const char* sm, int i, int q, int relu) {
    const float4* X4  = reinterpret_cast<const float4*>(sm + SM_XS);
    const int*  scol  = reinterpret_cast<const int*>(sm + SM_COL);
    const float* sval = reinterpret_cast<const float*>(sm + SM_VAL);
    const int*  srp   = reinterpret_cast<const int*>(sm + SM_RP);
    const int p0 = srp[i], p1 = srp[i + 1];
    float4 acc = make_float4(0.f, 0.f, 0.f, 0.f);
    for (int e = p0; e < p1; e++) {
        const float v = sval[e];          // broadcast across half-warp
        const int col = scol[e];          // broadcast
        const float4 x = X4[col * 16 + q];
        acc.x = fmaf(v, x.x, acc.x);
        acc.y = fmaf(v, x.y, acc.y);
        acc.z = fmaf(v, x.z, acc.z);
        acc.w = fmaf(v, x.w, acc.w);
    }
    if (relu) {
        acc.x = fmaxf(acc.x, 0.f); acc.y = fmaxf(acc.y, 0.f);
        acc.z = fmaxf(acc.z, 0.f); acc.w = fmaxf(acc.w, 0.f);
    }
    return acc;
}

// hilo variant: writes [M x Kpad] hi/lo bf16 (Kpad multiple of 64)
__global__ void __launch_bounds__(256)
spmm_batch_hilo_kernel(int mat, const float* __restrict__ Z,
                       __nv_bfloat16* __restrict__ hi, __nv_bfloat16* __restrict__ lo,
                       int d, int Kpad, int relu) {
    extern __shared__ __align__(16) char sm[];
    const int b = blockIdx.x;
    const float* Zb = Z + (size_t)b * N_NODES * d;
    spmm_stage_csr(sm, mat);
    const int w = threadIdx.x >> 5;
    const int lane = threadIdx.x & 31;
    const int half = lane >> 4;
    const int q = lane & 15;
    const int ntile = Kpad >> 6;
    for (int t = 0; t < ntile; t++) {
        const int dt = t * 64;
        int vw = d - dt;
        vw = vw < 0 ? 0 : (vw > 64 ? 64 : vw);
        if (t > 0) __syncthreads();
        spmm_stage_x(sm, Zb, d, dt, vw);
        __syncthreads();
        for (int r0 = 0; r0 < 256; r0 += 16) {
            const int i = r0 + w * 2 + half;
            if (i >= N_NODES) continue;
            const float4 a = spmm_gather_row(sm, i, q, relu);
            const size_t ob = ((size_t)b * N_NODES + i) * Kpad + dt + q * 4;
            __nv_bfloat16 h[4], l[4];
            const float v[4] = { a.x, a.y, a.z, a.w };
#pragma unroll
            for (int j = 0; j < 4; j++) {
                h[j] = __float2bfloat16_rn(v[j]);
                l[j] = __float2bfloat16_rn(v[j] - __bfloat162float(h[j]));
            }
            *reinterpret_cast<uint2*>(hi + ob) = *reinterpret_cast<uint2*>(h);
            *reinterpret_cast<uint2*>(lo + ob) = *reinterpret_cast<uint2*>(l);
        }
    }
}

// fp32 variant: writes [M x d] fp32
__global__ void __launch_bounds__(256)
spmm_batch_f32_kernel(int mat, const float* __restrict__ Z,
                      float* __restrict__ out, int d, int relu) {
    extern __shared__ __align__(16) char sm[];
    const int b = blockIdx.x;
    const float* Zb = Z + (size_t)b * N_NODES * d;
    spmm_stage_csr(sm, mat);
    const int w = threadIdx.x >> 5;
    const int lane = threadIdx.x & 31;
    const int half = lane >> 4;
    const int q = lane & 15;
    const int ntile = (d + 63) >> 6;
    for (int t = 0; t < ntile; t++) {
        const int dt = t * 64;
        int vw = d - dt;
        vw = vw > 64 ? 64 : vw;
        if (t > 0) __syncthreads();
        spmm_stage_x(sm, Zb, d, dt, vw);
        __syncthreads();
        const int vw4 = vw >> 2;
        for (int r0 = 0; r0 < 256; r0 += 16) {
            const int i = r0 + w * 2 + half;
            if (i >= N_NODES || q >= vw4) continue;
            const float4 a = spmm_gather_row(sm, i, q, relu);
            *reinterpret_cast<float4*>(out + ((size_t)b * N_NODES + i) * d + dt + q * 4) = a;
        }
    }
}

// ---------------- enc0: relu(x0*W0 + x1*W1 + rowsum*b) -> hi/lo (Kpad=448)
__device__ __forceinline__ void split_store(__nv_bfloat16* hi, __nv_bfloat16* lo,
                                            size_t off, float x) {
    const __nv_bfloat16 h = __float2bfloat16_rn(x);
    hi[off] = h;
    lo[off] = __float2bfloat16_rn(x - __bfloat162float(h));
}
__global__ void enc0_hilo_kernel(const float* __restrict__ X2, const float* __restrict__ W,
                                 const float* __restrict__ b,
                                 __nv_bfloat16* __restrict__ hi, __nv_bfloat16* __restrict__ lo) {
    const int idx = blockIdx.x * blockDim.x + threadIdx.x;  // M_ROWS * 112 float4-groups
    if (idx >= M_ROWS * 112) return;
    const int m = idx / 112;
    const int q = idx - m * 112;
    const size_t obase = (size_t)m * MAXKPAD + q * 4;
    if (q >= 100) {
        const __nv_bfloat16 z = __float2bfloat16_rn(0.f);
#pragma unroll
        for (int j = 0; j < 4; j++) { hi[obase + j] = z; lo[obase + j] = z; }
        return;
    }
    const float2 a = reinterpret_cast<const float2*>(X2)[m];
    const float4 w0 = reinterpret_cast<const float4*>(W)[q];
    const float4 w1 = reinterpret_cast<const float4*>(W + 400)[q];
    const float4 bv = reinterpret_cast<const float4*>(b)[q];
    const float sc = g_rowsum[0][m % N_NODES];
    float o[4];
    o[0] = fmaxf(fmaf(a.x, w0.x, fmaf(a.y, w1.x, sc * bv.x)), 0.f);
    o[1] = fmaxf(fmaf(a.x, w0.y, fmaf(a.y, w1.y, sc * bv.y)), 0.f);
    o[2] = fmaxf(fmaf(a.x, w0.z, fmaf(a.y, w1.z, sc * bv.z)), 0.f);
    o[3] = fmaxf(fmaf(a.x, w0.w, fmaf(a.y, w1.w, sc * bv.w)), 0.f);
#pragma unroll
    for (int j = 0; j < 4; j++) split_store(hi, lo, obase + j, o[j]);
}

// ---------------- weight prep: W[K,N] fp32 -> Wstack[Npad, 2*Kpad] bf16 --
// segments along k': [0,Kpad)=Whi^T, [Kpad,2Kpad)=Wlo^T
__global__ void prep_w_kernel(const float* __restrict__ W, int K, int N, int Kpad, int Npad) {
    const int t = blockIdx.x * blockDim.x + threadIdx.x;
    const int total = Npad * 2 * Kpad;
    if (t >= total) return;
    const int n = t / (2 * Kpad);
    const int kk = t - n * 2 * Kpad;
    const int seg = kk / Kpad;
    const int k = kk - seg * Kpad;
    float v = 0.f;
    if (n < N && k < K) v = W[(size_t)k * N + n];
    const __nv_bfloat16 h = __float2bfloat16_rn(v);
    g_wstack[t] = (seg == 1) ? __float2bfloat16_rn(v - __bfloat162float(h)) : h;
}

// ---------------- mma.sync bf16 GEMM, chunk-major 3-term fp32 emulation --
// Per K-chunk (32), stage Ahi/Alo/Whi/Wlo tiles together; issue
// Ahi*Whi + Alo*Whi + Ahi*Wlo into one accumulator. 2-stage cp.async.
#define ASTRIDE 80                          // bytes per smem row (64 + 16 pad)
#define GTILE   (128 * ASTRIDE)             // 10240 per tile
#define GSTAGE  (4 * GTILE)                 // Ahi Alo Bhi Blo
#define GEMM_SMEM (2 * GSTAGE)              // 81920

__global__ void __launch_bounds__(256, 2)
gemm_mma_kernel(const __nv_bfloat16* __restrict__ Ahi, const __nv_bfloat16* __restrict__ Alo,
                const __nv_bfloat16* __restrict__ Wst, const float* __restrict__ bias,
                int mat, int mode, float* __restrict__ C, int Kpad, int N) {
    extern __shared__ __align__(128) char gsm[];
    const uint32_t sbase = smem_u32(gsm);

    const int tid = threadIdx.x;
    const int lane = tid & 31;
    const int w = tid >> 5;
    const int warpM = (w & 3) * 32;
    const int warpN = (w >> 2) * 64;
    const int mBase = blockIdx.x * 128;
    const int nBase = blockIdx.y * 128;

    float acc[2][8][4];
#pragma unroll
    for (int i = 0; i < 2; i++)
#pragma unroll
        for (int j = 0; j < 8; j++)
#pragma unroll
            for (int q = 0; q < 4; q++) acc[i][j][q] = 0.f;

    // ldmatrix per-lane byte offsets
    const int arow = (lane & 7) + ((lane >> 3) & 1) * 8;
    const int acol = (lane >> 4) * 8;
    uint32_t aoff[2];
#pragma unroll
    for (int mt = 0; mt < 2; mt++)
        aoff[mt] = (uint32_t)((warpM + mt * 16 + arow) * ASTRIDE + acol * 2);
    const int bn = (lane >> 4) * 8 + (lane & 7);
    const int bk = ((lane >> 3) & 1) * 8;
    uint32_t boff[4];
#pragma unroll
    for (int j = 0; j < 4; j++)
        boff[j] = (uint32_t)((warpN + j * 16 + bn) * ASTRIDE + bk * 2);

    // cp.async staging: thread -> row tid>>1, 32B half (tid&1)
    const int ldrow = tid >> 1;
    const int ch0 = (tid & 1) * 2;
    const uint32_t stoff = (uint32_t)(ldrow * ASTRIDE + ch0 * 16);
    const int wrow = 2 * Kpad;
    const int nch = Kpad >> 5;
    const __nv_bfloat16* ArowH = Ahi + (size_t)(mBase + ldrow) * Kpad + ch0 * 8;
    const __nv_bfloat16* ArowL = Alo + (size_t)(mBase + ldrow) * Kpad + ch0 * 8;
    const __nv_bfloat16* BrowH = Wst + (size_t)(nBase + ldrow) * wrow + ch0 * 8;
    const __nv_bfloat16* BrowL = BrowH + Kpad;

    auto issue = [&](int c, int st) {
        const int k0 = c * 32;
        const uint32_t sb = sbase + st * GSTAGE + stoff;
        cpasync16(sb,                  ArowH + k0);
        cpasync16(sb + 16,             ArowH + k0 + 8);
        cpasync16(sb + GTILE,          ArowL + k0);
        cpasync16(sb + GTILE + 16,     ArowL + k0 + 8);
        cpasync16(sb + 2 * GTILE,      BrowH + k0);
        cpasync16(sb + 2 * GTILE + 16, BrowH + k0 + 8);
        cpasync16(sb + 3 * GTILE,      BrowL + k0);
        cpasync16(sb + 3 * GTILE + 16, BrowL + k0 + 8);
        cp_commit();
    };

    issue(0, 0);
    for (int c = 0; c < nch; c++) {
        const int st = c & 1;
        asm volatile("cp.async.wait_group 0;" ::: "memory");
        __syncthreads();
        if (c + 1 < nch) issue(c + 1, st ^ 1);

        const uint32_t stage = sbase + st * GSTAGE;
#pragma unroll
        for (int ks = 0; ks < 2; ks++) {
            uint32_t afH[2][4], afL[2][4];
#pragma unroll
            for (int mt = 0; mt < 2; mt++) {
                ldmx4(afH[mt][0], afH[mt][1], afH[mt][2], afH[mt][3],
                      stage + aoff[mt] + ks * 32);
                ldmx4(afL[mt][0], afL[mt][1], afL[mt][2], afL[mt][3],
                      stage + GTILE + aoff[mt] + ks * 32);
            }
#pragma unroll
            for (int j = 0; j < 4; j++) {
                uint32_t b0, b1, b2, b3;
                ldmx4(b0, b1, b2, b3, stage + 2 * GTILE + boff[j] + ks * 32);
#pragma unroll
                for (int mt = 0; mt < 2; mt++) {
                    mma16816(acc[mt][2 * j],     afH[mt], b0, b1);
                    mma16816(acc[mt][2 * j + 1], afH[mt], b2, b3);
                    mma16816(acc[mt][2 * j],     afL[mt], b0, b1);
                    mma16816(acc[mt][2 * j + 1], afL[mt], b2, b3);
                }
                ldmx4(b0, b1, b2, b3, stage + 3 * GTILE + boff[j] + ks * 32);
#pragma unroll
                for (int mt = 0; mt < 2; mt++) {
                    mma16816(acc[mt][2 * j],     afH[mt], b0, b1);
                    mma16816(acc[mt][2 * j + 1], afH[mt], b2, b3);
                }
            }
        }
    }

    // epilogue
#pragma unroll
    for (int mt = 0; mt < 2; mt++) {
        const int r0 = mBase + warpM + mt * 16 + (lane >> 2);
        const int r1 = r0 + 8;
        const float s0 = (mode == 1) ? g_rowsum[mat][r0 % N_NODES] : 1.f;
        const float s1 = (mode == 1) ? g_rowsum[mat][r1 % N_NODES] : 1.f;
#pragma unroll
        for (int nt = 0; nt < 8; nt++) {
            const int n = nBase + warpN + nt * 8 + (lane & 3) * 2;
            if (n >= N) continue;
            const float b0 = bias[n], b1 = bias[n + 1];
            float o0 = acc[mt][nt][0] + b0 * s0;
            float o1 = acc[mt][nt][1] + b1 * s0;
            float o2 = acc[mt][nt][2] + b0 * s1;
            float o3 = acc[mt][nt][3] + b1 * s1;
            if (mode == 1) {
                o0 = fmaxf(o0, 0.f); o1 = fmaxf(o1, 0.f);
                o2 = fmaxf(o2, 0.f); o3 = fmaxf(o3, 0.f);
            }
            *reinterpret_cast<float2*>(C + (size_t)r0 * N + n) = make_float2(o0, o1);
            *reinterpret_cast<float2*>(C + (size_t)r1 * N + n) = make_float2(o2, o3);
        }
    }
}

// ---------------- thin GEMM for N=2 (dec2): warp per row -----------------
__global__ void gemm_thin_kernel(const float* __restrict__ X, const float* __restrict__ Wt,
                                 const float* __restrict__ bias, float* __restrict__ out, int K) {
    __shared__ float Ws[2 * MAXD];
    for (int i = threadIdx.x; i < 2 * K; i += blockDim.x) Ws[i] = Wt[i];
    __syncthreads();
    const int warp = threadIdx.x >> 5, lane = threadIdx.x & 31;
    const int row = blockIdx.x * 8 + warp;
    if (row >= M_ROWS) return;
    const float* x = X + (size_t)row * K;
    float a0 = 0.f, a1 = 0.f;
    for (int k = lane; k < K; k += 32) {
        const float xv = x[k];
        a0 = fmaf(xv, Ws[2 * k], a0);
        a1 = fmaf(xv, Ws[2 * k + 1], a1);
    }
#pragma unroll
    for (int off = 16; off; off >>= 1) {
        a0 += __shfl_down_sync(0xffffffffu, a0, off);
        a1 += __shfl_down_sync(0xffffffffu, a1, off);
    }
    if (lane == 0) {
        out[2 * row]     = a0 + bias[0];
        out[2 * row + 1] = a1 + bias[1];
    }
}

// ---------------- launch -------------------------------------------------
extern "C" void kernel_launch(void* const* d_in, const int* in_sizes, int n_in,
                              void* d_out, int out_size) {
    const float* H   = (const float*)d_in[0];
    const float* smv = (const float*)d_in[1];
    const float* spv = (const float*)d_in[2];
    const float* W[6];
    const float* bb[6];
    for (int i = 0; i < 6; i++) {
        W[i]  = (const float*)d_in[3 + 2 * i];
        bb[i] = (const float*)d_in[4 + 2 * i];
    }
    const int* smi = (const int*)d_in[15];
    const int* spi = (const int*)d_in[16];
    float* out = (float*)d_out;

    float *bufA, *bufB;
    __nv_bfloat16 *hi, *lo, *wst;
    cudaGetSymbolAddress((void**)&bufA, g_bufA);
    cudaGetSymbolAddress((void**)&bufB, g_bufB);
    cudaGetSymbolAddress((void**)&hi, g_hi);
    cudaGetSymbolAddress((void**)&lo, g_lo);
    cudaGetSymbolAddress((void**)&wst, g_wstack);

    cudaFuncSetAttribute(gemm_mma_kernel, cudaFuncAttributeMaxDynamicSharedMemorySize, GEMM_SMEM);
    cudaFuncSetAttribute(spmm_batch_hilo_kernel, cudaFuncAttributeMaxDynamicSharedMemorySize, SPMM_SMEM);
    cudaFuncSetAttribute(spmm_batch_f32_kernel, cudaFuncAttributeMaxDynamicSharedMemorySize, SPMM_SMEM);

    const int tpb = 256;
    const int mblk = M_ROWS / 128;  // 1020

    build_csr_kernel<<<2, 256>>>(smi, smv, spi, spv);

    // enc0 (2->400): SpMM(sm) on d=2, fused layer -> hi/lo (Kpad=448)
    spmm_d2_kernel<<<(M_ROWS + tpb - 1) / tpb, tpb>>>(0, H, bufA, 0);
    enc0_hilo_kernel<<<(M_ROWS * 112 + tpb - 1) / tpb, tpb>>>(bufA, W[0], bb[0], hi, lo);

    // enc1 (400->300), Kpad=448, Npad=384
    prep_w_kernel<<<(384 * 2 * 448 + tpb - 1) / tpb, tpb>>>(W[1], 400, 300, 448, 384);
    gemm_mma_kernel<<<dim3(mblk, 3), 256, GEMM_SMEM>>>(hi, lo, wst, bb[1], 0, 0, bufB, 448, 300);
    spmm_batch_hilo_kernel<<<BATCH, 256, SPMM_SMEM>>>(0, bufB, hi, lo, 300, 320, 1);

    // enc2 (300->100), Kpad=320, Npad=128
    prep_w_kernel<<<(128 * 2 * 320 + tpb - 1) / tpb, tpb>>>(W[2], 300, 100, 320, 128);
    gemm_mma_kernel<<<dim3(mblk, 1), 256, GEMM_SMEM>>>(hi, lo, wst, bb[2], 0, 0, bufA, 320, 100);
    spmm_batch_f32_kernel<<<BATCH, 256, SPMM_SMEM>>>(0, bufA, bufB, 100, 1);

    // dec0 (100->300): SpMM(sp)-first -> hi/lo (Kpad=128); GEMM mode1
    spmm_batch_hilo_kernel<<<BATCH, 256, SPMM_SMEM>>>(1, bufB, hi, lo, 100, 128, 0);
    prep_w_kernel<<<(384 * 2 * 128 + tpb - 1) / tpb, tpb>>>(W[3], 100, 300, 128, 384);
    gemm_mma_kernel<<<dim3(mblk, 3), 256, GEMM_SMEM>>>(hi, lo, wst, bb[3], 1, 1, bufA, 128, 300);

    // dec1 (300->400): SpMM(sp)-first -> hi/lo (Kpad=320); GEMM mode1
    spmm_batch_hilo_kernel<<<BATCH, 256, SPMM_SMEM>>>(1, bufA, hi, lo, 300, 320, 0);
    prep_w_kernel<<<(512 * 2 * 320 + tpb - 1) / tpb, tpb>>>(W[4], 300, 400, 320, 512);
    gemm_mma_kernel<<<dim3(mblk, 4), 256, GEMM_SMEM>>>(hi, lo, wst, bb[4], 1, 1, bufB, 320, 400);

    // dec2 (400->2): thin GEMM+bias, then SpMM(sp)+ReLU on d=2 into d_out
    gemm_thin_kernel<<<M_ROWS / 8, 256>>>(bufB, W[5], bb[5], bufA, 400);
    spmm_d2_kernel<<<(M_ROWS + tpb - 1) / tpb, tpb>>>(1, bufA, out, 1);
}

// round 15
// speedup vs baseline: 1.3551x; 1.0470x over previous
#include <cuda_runtime.h>
#include <cuda_bf16.h>
#include <cstdint>

#define N_NODES 255
#define NNZ_E   2550
#define BATCH   512
#define M_ROWS  (BATCH * N_NODES)   // 130560 (divisible by 128)
#define MAXD    400
#define MAXKPAD 448

// ---------------- device scratch (no allocations allowed) ----------------
__device__ __align__(256) float         g_bufA[M_ROWS * MAXD];
__device__ __align__(256) float         g_bufB[M_ROWS * MAXD];
__device__ __align__(256) __nv_bfloat16 g_hi[M_ROWS * MAXKPAD];
__device__ __align__(256) __nv_bfloat16 g_lo[M_ROWS * MAXKPAD];
__device__ __align__(256) __nv_bfloat16 g_wstack[720896];   // 4 layer regions
__device__ int   g_rowptr[2][N_NODES + 1];
__device__ int   g_cols[2][NNZ_E];
__device__ float g_vals[2][NNZ_E];
__device__ float g_rowsum[2][N_NODES];

// wstack offsets per layer (elements)
#define WOFF_ENC1 0        // 320 x 2*416 = 266240
#define WOFF_ENC2 266240   // 128 x 2*320 =  81920
#define WOFF_DEC0 348160   // 320 x 2*128 =  81920
#define WOFF_DEC1 430080   // 448 x 2*320 = 286720

// ================= PTX helpers =================
__device__ __forceinline__ uint32_t smem_u32(const void* p) {
    uint32_t a;
    asm("{ .reg .u64 t; cvta.to.shared.u64 t, %1; cvt.u32.u64 %0, t; }" : "=r"(a) : "l"(p));
    return a;
}
__device__ __forceinline__ void ldmx4(uint32_t& r0, uint32_t& r1, uint32_t& r2, uint32_t& r3,
                                      uint32_t addr) {
    asm volatile("ldmatrix.sync.aligned.m8n8.x4.shared.b16 {%0,%1,%2,%3}, [%4];"
                 : "=r"(r0), "=r"(r1), "=r"(r2), "=r"(r3) : "r"(addr));
}
__device__ __forceinline__ void mma16816(float* d, const uint32_t* a, uint32_t b0, uint32_t b1) {
    asm volatile(
        "mma.sync.aligned.m16n8k16.row.col.f32.bf16.bf16.f32 "
        "{%0,%1,%2,%3}, {%4,%5,%6,%7}, {%8,%9}, {%0,%1,%2,%3};"
        : "+f"(d[0]), "+f"(d[1]), "+f"(d[2]), "+f"(d[3])
        : "r"(a[0]), "r"(a[1]), "r"(a[2]), "r"(a[3]), "r"(b0), "r"(b1));
}
__device__ __forceinline__ void cpasync16(uint32_t dst, const void* src) {
    asm volatile("cp.async.cg.shared.global [%0], [%1], 16;" :: "r"(dst), "l"(src) : "memory");
}
__device__ __forceinline__ void cp_commit() {
    asm volatile("cp.async.commit_group;" ::: "memory");
}

// ---------------- deterministic COO -> CSR build (1 block per matrix) ----
__global__ void build_csr_kernel(const int* __restrict__ sm_idx, const float* __restrict__ sm_val,
                                 const int* __restrict__ sp_idx, const float* __restrict__ sp_val) {
    __shared__ int   srow[NNZ_E];
    __shared__ int   scolg[NNZ_E];
    __shared__ float sval[NNZ_E];
    __shared__ int   rptr[N_NODES + 1];
    __shared__ int   cnt[N_NODES];
    const int mat = blockIdx.x;
    const int*   idx = mat ? sp_idx : sm_idx;
    const float* val = mat ? sp_val : sm_val;
    const int t = threadIdx.x;

    for (int e = t; e < NNZ_E; e += blockDim.x) {
        srow[e]  = idx[2 * e];
        scolg[e] = idx[2 * e + 1];
        sval[e]  = val[e];
    }
    for (int i = t; i < N_NODES; i += blockDim.x) cnt[i] = 0;
    __syncthreads();
    for (int e = t; e < NNZ_E; e += blockDim.x) atomicAdd(&cnt[srow[e]], 1);
    __syncthreads();
    if (t == 0) {
        int s = 0;
        for (int i = 0; i < N_NODES; i++) { rptr[i] = s; s += cnt[i]; }
        rptr[N_NODES] = s;
    }
    __syncthreads();
    for (int i = t; i < N_NODES; i += blockDim.x) {
        int c = 0;
        float s = 0.f;
        const int base = rptr[i];
        for (int e = 0; e < NNZ_E; e++) {
            if (srow[e] == i) {
                g_cols[mat][base + c] = scolg[e];
                g_vals[mat][base + c] = sval[e];
                c++;
                s += sval[e];
            }
        }
        g_rowsum[mat][i] = s;
    }
    for (int i = t; i <= N_NODES; i += blockDim.x) g_rowptr[mat][i] = rptr[i];
}

// ---------------- SpMM, feature dim = 2 ----------------------------------
__global__ void spmm_d2_kernel(int mat, const float* __restrict__ X,
                               float* __restrict__ out, int relu) {
    const int t = blockIdx.x * blockDim.x + threadIdx.x;
    if (t >= M_ROWS) return;
    const int b = t / N_NODES;
    const int i = t - b * N_NODES;
    const int p0 = g_rowptr[mat][i], p1 = g_rowptr[mat][i + 1];
    const float2* Xb = reinterpret_cast<const float2*>(X) + (size_t)b * N_NODES;
    float a0 = 0.f, a1 = 0.f;
    for (int e = p0; e < p1; e++) {
        const float v = g_vals[mat][e];
        const float2 x = Xb[g_cols[mat][e]];
        a0 = fmaf(v, x.x, a0);
        a1 = fmaf(v, x.y, a1);
    }
    if (relu) { a0 = fmaxf(a0, 0.f); a1 = fmaxf(a1, 0.f); }
    reinterpret_cast<float2*>(out)[t] = make_float2(a0, a1);
}

// ======== per-batch smem SpMM: half-warp per row, lane = q ==============
#define SPMM_SMEM 86720
#define SM_XS   0
#define SM_COL  65280
#define SM_VAL  75480
#define SM_RP   85680

__device__ __forceinline__ void spmm_stage_csr(char* sm, int mat) {
    int*   scol = reinterpret_cast<int*>(sm + SM_COL);
    float* sval = reinterpret_cast<float*>(sm + SM_VAL);
    int*   srp  = reinterpret_cast<int*>(sm + SM_RP);
    const int tid = threadIdx.x;
    for (int e = tid; e < NNZ_E; e += 256) { scol[e] = g_cols[mat][e]; sval[e] = g_vals[mat][e]; }
    if (tid <= N_NODES) srp[tid] = g_rowptr[mat][tid];
}

__device__ __forceinline__ void spmm_stage_x(char* sm, const float* Zb, int d, int dt, int vw) {
    float4* X4 = reinterpret_cast<float4*>(sm + SM_XS);
    const int tid = threadIdx.x;
    const int vw4 = vw >> 2;
    if (vw4 < 16) {
        const int pw = 16 - vw4;
        const float4 z = make_float4(0.f, 0.f, 0.f, 0.f);
        for (int it = tid; it < N_NODES * pw; it += 256) {
            const int i = it / pw;
            const int q = vw4 + (it - i * pw);
            X4[i * 16 + q] = z;
        }
    }
    for (int it = tid; it < N_NODES * vw4; it += 256) {
        const int i = it / vw4;
        const int q = it - i * vw4;
        X4[i * 16 + q] = *reinterpret_cast<const float4*>(Zb + (size_t)i * d + dt + q * 4);
    }
}

__device__ __forceinline__ float4 spmm_gather_row(const char* sm, int i, int q, int relu) {
    const float4* X4  = reinterpret_cast<const float4*>(sm + SM_XS);
    const int*  scol  = reinterpret_cast<const int*>(sm + SM_COL);
    const float* sval = reinterpret_cast<const float*>(sm + SM_VAL);
    const int*  srp   = reinterpret_cast<const int*>(sm + SM_RP);
    const int p0 = srp[i], p1 = srp[i + 1];
    float4 acc = make_float4(0.f, 0.f, 0.f, 0.f);
    for (int e = p0; e < p1; e++) {
        const float v = sval[e];
        const int col = scol[e];
        const float4 x = X4[col * 16 + q];
        acc.x = fmaf(v, x.x, acc.x);
        acc.y = fmaf(v, x.y, acc.y);
        acc.z = fmaf(v, x.z, acc.z);
        acc.w = fmaf(v, x.w, acc.w);
    }
    if (relu) {
        acc.x = fmaxf(acc.x, 0.f); acc.y = fmaxf(acc.y, 0.f);
        acc.z = fmaxf(acc.z, 0.f); acc.w = fmaxf(acc.w, 0.f);
    }
    return acc;
}

__global__ void __launch_bounds__(256)
spmm_batch_hilo_kernel(int mat, const float* __restrict__ Z,
                       __nv_bfloat16* __restrict__ hi, __nv_bfloat16* __restrict__ lo,
                       int d, int Kpad, int relu) {
    extern __shared__ __align__(16) char sm[];
    const int b = blockIdx.x;
    const float* Zb = Z + (size_t)b * N_NODES * d;
    spmm_stage_csr(sm, mat);
    const int w = threadIdx.x >> 5;
    const int lane = threadIdx.x & 31;
    const int half = lane >> 4;
    const int q = lane & 15;
    const int ntile = Kpad >> 6;
    for (int t = 0; t < ntile; t++) {
        const int dt = t * 64;
        int vw = d - dt;
        vw = vw < 0 ? 0 : (vw > 64 ? 64 : vw);
        if (t > 0) __syncthreads();
        spmm_stage_x(sm, Zb, d, dt, vw);
        __syncthreads();
        for (int r0 = 0; r0 < 256; r0 += 16) {
            const int i = r0 + w * 2 + half;
            if (i >= N_NODES) continue;
            const float4 a = spmm_gather_row(sm, i, q, relu);
            const size_t ob = ((size_t)b * N_NODES + i) * Kpad + dt + q * 4;
            __nv_bfloat16 h[4], l[4];
            const float v[4] = { a.x, a.y, a.z, a.w };
#pragma unroll
            for (int j = 0; j < 4; j++) {
                h[j] = __float2bfloat16_rn(v[j]);
                l[j] = __float2bfloat16_rn(v[j] - __bfloat162float(h[j]));
            }
            *reinterpret_cast<uint2*>(hi + ob) = *reinterpret_cast<uint2*>(h);
            *reinterpret_cast<uint2*>(lo + ob) = *reinterpret_cast<uint2*>(l);
        }
    }
}

__global__ void __launch_bounds__(256)
spmm_batch_f32_kernel(int mat, const float* __restrict__ Z,
                      float* __restrict__ out, int d, int relu) {
    extern __shared__ __align__(16) char sm[];
    const int b = blockIdx.x;
    const float* Zb = Z + (size_t)b * N_NODES * d;
    spmm_stage_csr(sm, mat);
    const int w = threadIdx.x >> 5;
    const int lane = threadIdx.x & 31;
    const int half = lane >> 4;
    const int q = lane & 15;
    const int ntile = (d + 63) >> 6;
    for (int t = 0; t < ntile; t++) {
        const int dt = t * 64;
        int vw = d - dt;
        vw = vw > 64 ? 64 : vw;
        if (t > 0) __syncthreads();
        spmm_stage_x(sm, Zb, d, dt, vw);
        __syncthreads();
        const int vw4 = vw >> 2;
        for (int r0 = 0; r0 < 256; r0 += 16) {
            const int i = r0 + w * 2 + half;
            if (i >= N_NODES || q >= vw4) continue;
            const float4 a = spmm_gather_row(sm, i, q, relu);
            *reinterpret_cast<float4*>(out + ((size_t)b * N_NODES + i) * d + dt + q * 4) = a;
        }
    }
}

// ---------------- enc0: relu(x0*W0 + x1*W1 + rowsum*b) -> hi/lo, stride Kpad
__device__ __forceinline__ void split_store(__nv_bfloat16* hi, __nv_bfloat16* lo,
                                            size_t off, float x) {
    const __nv_bfloat16 h = __float2bfloat16_rn(x);
    hi[off] = h;
    lo[off] = __float2bfloat16_rn(x - __bfloat162float(h));
}
__global__ void enc0_hilo_kernel(const float* __restrict__ X2, const float* __restrict__ W,
                                 const float* __restrict__ b,
                                 __nv_bfloat16* __restrict__ hi, __nv_bfloat16* __restrict__ lo,
                                 int Kpad) {
    const int ng = Kpad >> 2;   // float4-groups per row (104 for 416)
    const int idx = blockIdx.x * blockDim.x + threadIdx.x;
    if (idx >= M_ROWS * ng) return;
    const int m = idx / ng;
    const int q = idx - m * ng;
    const size_t obase = (size_t)m * Kpad + q * 4;
    if (q >= 100) {
        const __nv_bfloat16 z = __float2bfloat16_rn(0.f);
#pragma unroll
        for (int j = 0; j < 4; j++) { hi[obase + j] = z; lo[obase + j] = z; }
        return;
    }
    const float2 a = reinterpret_cast<const float2*>(X2)[m];
    const float4 w0 = reinterpret_cast<const float4*>(W)[q];
    const float4 w1 = reinterpret_cast<const float4*>(W + 400)[q];
    const float4 bv = reinterpret_cast<const float4*>(b)[q];
    const float sc = g_rowsum[0][m % N_NODES];
    float o[4];
    o[0] = fmaxf(fmaf(a.x, w0.x, fmaf(a.y, w1.x, sc * bv.x)), 0.f);
    o[1] = fmaxf(fmaf(a.x, w0.y, fmaf(a.y, w1.y, sc * bv.y)), 0.f);
    o[2] = fmaxf(fmaf(a.x, w0.z, fmaf(a.y, w1.z, sc * bv.z)), 0.f);
    o[3] = fmaxf(fmaf(a.x, w0.w, fmaf(a.y, w1.w, sc * bv.w)), 0.f);
#pragma unroll
    for (int j = 0; j < 4; j++) split_store(hi, lo, obase + j, o[j]);
}

// ---------------- weight prep: W[K,N] fp32 -> dst[Npad, 2*Kpad] bf16 -----
__global__ void prep_w_kernel(const float* __restrict__ W, __nv_bfloat16* __restrict__ dst,
                              int K, int N, int Kpad, int Npad) {
    const int t = blockIdx.x * blockDim.x + threadIdx.x;
    const int total = Npad * 2 * Kpad;
    if (t >= total) return;
    const int n = t / (2 * Kpad);
    const int kk = t - n * 2 * Kpad;
    const int seg = kk / Kpad;
    const int k = kk - seg * Kpad;
    float v = 0.f;
    if (n < N && k < K) v = W[(size_t)k * N + n];
    const __nv_bfloat16 h = __float2bfloat16_rn(v);
    dst[t] = (seg == 1) ? __float2bfloat16_rn(v - __bfloat162float(h)) : h;
}

// ---------------- mma.sync bf16 GEMM, chunk-major 3-term, BN=128 ---------
#define ASTRIDE 80
#define GTILE   (128 * ASTRIDE)             // 10240
#define GSTAGE  (4 * GTILE)                 // Ahi Alo Bhi Blo
#define GEMM_SMEM (2 * GSTAGE)              // 81920

__global__ void __launch_bounds__(256, 2)
gemm_mma_kernel(const __nv_bfloat16* __restrict__ Ahi, const __nv_bfloat16* __restrict__ Alo,
                const __nv_bfloat16* __restrict__ Wst, const float* __restrict__ bias,
                int mat, int mode, float* __restrict__ C, int Kpad, int N) {
    extern __shared__ __align__(128) char gsm[];
    const uint32_t sbase = smem_u32(gsm);

    const int tid = threadIdx.x;
    const int lane = tid & 31;
    const int w = tid >> 5;
    const int warpM = (w & 3) * 32;
    const int warpN = (w >> 2) * 64;
    const int mBase = blockIdx.x * 128;
    const int nBase = blockIdx.y * 128;

    float acc[2][8][4];
#pragma unroll
    for (int i = 0; i < 2; i++)
#pragma unroll
        for (int j = 0; j < 8; j++)
#pragma unroll
            for (int q = 0; q < 4; q++) acc[i][j][q] = 0.f;

    const int arow = (lane & 7) + ((lane >> 3) & 1) * 8;
    const int acol = (lane >> 4) * 8;
    uint32_t aoff[2];
#pragma unroll
    for (int mt = 0; mt < 2; mt++)
        aoff[mt] = (uint32_t)((warpM + mt * 16 + arow) * ASTRIDE + acol * 2);
    const int bn = (lane >> 4) * 8 + (lane & 7);
    const int bk = ((lane >> 3) & 1) * 8;
    uint32_t boff[4];
#pragma unroll
    for (int j = 0; j < 4; j++)
        boff[j] = (uint32_t)((warpN + j * 16 + bn) * ASTRIDE + bk * 2);

    const int ldrow = tid >> 1;
    const int ch0 = (tid & 1) * 2;
    const uint32_t stoff = (uint32_t)(ldrow * ASTRIDE + ch0 * 16);
    const int wrow = 2 * Kpad;
    const int nch = Kpad >> 5;
    const __nv_bfloat16* ArowH = Ahi + (size_t)(mBase + ldrow) * Kpad + ch0 * 8;
    const __nv_bfloat16* ArowL = Alo + (size_t)(mBase + ldrow) * Kpad + ch0 * 8;
    const __nv_bfloat16* BrowH = Wst + (size_t)(nBase + ldrow) * wrow + ch0 * 8;
    const __nv_bfloat16* BrowL = BrowH + Kpad;

    auto issue = [&](int c, int st) {
        const int k0 = c * 32;
        const uint32_t sb = sbase + st * GSTAGE + stoff;
        cpasync16(sb,                  ArowH + k0);
        cpasync16(sb + 16,             ArowH + k0 + 8);
        cpasync16(sb + GTILE,          ArowL + k0);
        cpasync16(sb + GTILE + 16,     ArowL + k0 + 8);
        cpasync16(sb + 2 * GTILE,      BrowH + k0);
        cpasync16(sb + 2 * GTILE + 16, BrowH + k0 + 8);
        cpasync16(sb + 3 * GTILE,      BrowL + k0);
        cpasync16(sb + 3 * GTILE + 16, BrowL + k0 + 8);
        cp_commit();
    };

    issue(0, 0);
    for (int c = 0; c < nch; c++) {
        const int st = c & 1;
        asm volatile("cp.async.wait_group 0;" ::: "memory");
        __syncthreads();
        if (c + 1 < nch) issue(c + 1, st ^ 1);

        const uint32_t stage = sbase + st * GSTAGE;
#pragma unroll
        for (int ks = 0; ks < 2; ks++) {
            uint32_t afH[2][4], afL[2][4];
#pragma unroll
            for (int mt = 0; mt < 2; mt++) {
                ldmx4(afH[mt][0], afH[mt][1], afH[mt][2], afH[mt][3],
                      stage + aoff[mt] + ks * 32);
                ldmx4(afL[mt][0], afL[mt][1], afL[mt][2], afL[mt][3],
                      stage + GTILE + aoff[mt] + ks * 32);
            }
#pragma unroll
            for (int j = 0; j < 4; j++) {
                uint32_t b0, b1, b2, b3;
                ldmx4(b0, b1, b2, b3, stage + 2 * GTILE + boff[j] + ks * 32);
#pragma unroll
                for (int mt = 0; mt < 2; mt++) {
                    mma16816(acc[mt][2 * j],     afH[mt], b0, b1);
                    mma16816(acc[mt][2 * j + 1], afH[mt], b2, b3);
                    mma16816(acc[mt][2 * j],     afL[mt], b0, b1);
                    mma16816(acc[mt][2 * j + 1], afL[mt], b2, b3);
                }
                ldmx4(b0, b1, b2, b3, stage + 3 * GTILE + boff[j] + ks * 32);
#pragma unroll
                for (int mt = 0; mt < 2; mt++) {
                    mma16816(acc[mt][2 * j],     afH[mt], b0, b1);
                    mma16816(acc[mt][2 * j + 1], afH[mt], b2, b3);
                }
            }
        }
    }

#pragma unroll
    for (int mt = 0; mt < 2; mt++) {
        const int r0 = mBase + warpM + mt * 16 + (lane >> 2);
        const int r1 = r0 + 8;
        const float s0 = (mode == 1) ? g_rowsum[mat][r0 % N_NODES] : 1.f;
        const float s1 = (mode == 1) ? g_rowsum[mat][r1 % N_NODES] : 1.f;
#pragma unroll
        for (int nt = 0; nt < 8; nt++) {
            const int n = nBase + warpN + nt * 8 + (lane & 3) * 2;
            if (n >= N) continue;
            const float b0 = bias[n], b1 = bias[n + 1];
            float o0 = acc[mt][nt][0] + b0 * s0;
            float o1 = acc[mt][nt][1] + b1 * s0;
            float o2 = acc[mt][nt][2] + b0 * s1;
            float o3 = acc[mt][nt][3] + b1 * s1;
            if (mode == 1) {
                o0 = fmaxf(o0, 0.f); o1 = fmaxf(o1, 0.f);
                o2 = fmaxf(o2, 0.f); o3 = fmaxf(o3, 0.f);
            }
            *reinterpret_cast<float2*>(C + (size_t)r0 * N + n) = make_float2(o0, o1);
            *reinterpret_cast<float2*>(C + (size_t)r1 * N + n) = make_float2(o2, o3);
        }
    }
}

// ---------------- BN=64 remainder GEMM: 8 warps stacked in M -------------
#define BTILE64 (64 * ASTRIDE)                      // 5120
#define GSTAGE64 (2 * GTILE + 2 * BTILE64)          // 30720
#define GEMM_SMEM64 (2 * GSTAGE64)                  // 61440

__global__ void __launch_bounds__(256, 2)
gemm_mma64_kernel(const __nv_bfloat16* __restrict__ Ahi, const __nv_bfloat16* __restrict__ Alo,
                  const __nv_bfloat16* __restrict__ Wst, const float* __restrict__ bias,
                  int mat, int mode, float* __restrict__ C, int Kpad, int N, int n0) {
    extern __shared__ __align__(128) char gsm[];
    const uint32_t sbase = smem_u32(gsm);

    const int tid = threadIdx.x;
    const int lane = tid & 31;
    const int w = tid >> 5;
    const int warpM = w * 16;          // 8 warps x 16 rows = 128
    const int mBase = blockIdx.x * 128;

    float acc[8][4];
#pragma unroll
    for (int j = 0; j < 8; j++)
#pragma unroll
        for (int q = 0; q < 4; q++) acc[j][q] = 0.f;

    const int arow = (lane & 7) + ((lane >> 3) & 1) * 8;
    const int acol = (lane >> 4) * 8;
    const uint32_t aoff = (uint32_t)((warpM + arow) * ASTRIDE + acol * 2);
    const int bn = (lane >> 4) * 8 + (lane & 7);
    const int bk = ((lane >> 3) & 1) * 8;
    uint32_t boff[4];
#pragma unroll
    for (int j = 0; j < 4; j++)
        boff[j] = (uint32_t)((j * 16 + bn) * ASTRIDE + bk * 2);

    const int ldrow = tid >> 1;
    const int ch0 = (tid & 1) * 2;
    const uint32_t stoffA = (uint32_t)(ldrow * ASTRIDE + ch0 * 16);
    const int wrow = 2 * Kpad;
    const int nch = Kpad >> 5;
    const __nv_bfloat16* ArowH = Ahi + (size_t)(mBase + ldrow) * Kpad + ch0 * 8;
    const __nv_bfloat16* ArowL = Alo + (size_t)(mBase + ldrow) * Kpad + ch0 * 8;
    // B: 64 rows; threads 0..127 stage
    const int brow = tid >> 1;         // 0..63 when tid<128
    const uint32_t stoffB = (uint32_t)(brow * ASTRIDE + ch0 * 16);
    const __nv_bfloat16* BrowH = Wst + (size_t)(n0 + brow) * wrow + ch0 * 8;
    const __nv_bfloat16* BrowL = BrowH + Kpad;

    auto issue = [&](int c, int st) {
        const int k0 = c * 32;
        const uint32_t sb = sbase + st * GSTAGE64;
        cpasync16(sb + stoffA,               ArowH + k0);
        cpasync16(sb + stoffA + 16,          ArowH + k0 + 8);
        cpasync16(sb + GTILE + stoffA,       ArowL + k0);
        cpasync16(sb + GTILE + stoffA + 16,  ArowL + k0 + 8);
        if (tid < 128) {
            cpasync16(sb + 2 * GTILE + stoffB,                ArowH == nullptr ? nullptr : BrowH + k0);
            cpasync16(sb + 2 * GTILE + stoffB + 16,           BrowH + k0 + 8);
            cpasync16(sb + 2 * GTILE + BTILE64 + stoffB,      BrowL + k0);
            cpasync16(sb + 2 * GTILE + BTILE64 + stoffB + 16, BrowL + k0 + 8);
        }
        cp_commit();
    };

    issue(0, 0);
    for (int c = 0; c < nch; c++) {
        const int st = c & 1;
        asm volatile("cp.async.wait_group 0;" ::: "memory");
        __syncthreads();
        if (c + 1 < nch) issue(c + 1, st ^ 1);

        const uint32_t stage = sbase + st * GSTAGE64;
#pragma unroll
        for (int ks = 0; ks < 2; ks++) {
            uint32_t afH[4], afL[4];
            ldmx4(afH[0], afH[1], afH[2], afH[3], stage + aoff + ks * 32);
            ldmx4(afL[0], afL[1], afL[2], afL[3], stage + GTILE + aoff + ks * 32);
#pragma unroll
            for (int j = 0; j < 4; j++) {
                uint32_t b0, b1, b2, b3;
                ldmx4(b0, b1, b2, b3, stage + 2 * GTILE + boff[j] + ks * 32);
                mma16816(acc[2 * j],     afH, b0, b1);
                mma16816(acc[2 * j + 1], afH, b2, b3);
                mma16816(acc[2 * j],     afL, b0, b1);
                mma16816(acc[2 * j + 1], afL, b2, b3);
                ldmx4(b0, b1, b2, b3, stage + 2 * GTILE + BTILE64 + boff[j] + ks * 32);
                mma16816(acc[2 * j],     afH, b0, b1);
                mma16816(acc[2 * j + 1], afH, b2, b3);
            }
        }
    }

    const int r0 = mBase + warpM + (lane >> 2);
    const int r1 = r0 + 8;
    const float s0 = (mode == 1) ? g_rowsum[mat][r0 % N_NODES] : 1.f;
    const float s1 = (mode == 1) ? g_rowsum[mat][r1 % N_NODES] : 1.f;
#pragma unroll
    for (int nt = 0; nt < 8; nt++) {
        const int n = n0 + nt * 8 + (lane & 3) * 2;
        if (n >= N) continue;
        const float b0 = bias[n], b1 = bias[n + 1];
        float o0 = acc[nt][0] + b0 * s0;
        float o1 = acc[nt][1] + b1 * s0;
        float o2 = acc[nt][2] + b0 * s1;
        float o3 = acc[nt][3] + b1 * s1;
        if (mode == 1) {
            o0 = fmaxf(o0, 0.f); o1 = fmaxf(o1, 0.f);
            o2 = fmaxf(o2, 0.f); o3 = fmaxf(o3, 0.f);
        }
        *reinterpret_cast<float2*>(C + (size_t)r0 * N + n) = make_float2(o0, o1);
        *reinterpret_cast<float2*>(C + (size_t)r1 * N + n) = make_float2(o2, o3);
    }
}

// ---------------- thin GEMM for N=2 (dec2): warp per row -----------------
__global__ void gemm_thin_kernel(const float* __restrict__ X, const float* __restrict__ Wt,
                                 const float* __restrict__ bias, float* __restrict__ out, int K) {
    __shared__ float Ws[2 * MAXD];
    for (int i = threadIdx.x; i < 2 * K; i += blockDim.x) Ws[i] = Wt[i];
    __syncthreads();
    const int warp = threadIdx.x >> 5, lane = threadIdx.x & 31;
    const int row = blockIdx.x * 8 + warp;
    if (row >= M_ROWS) return;
    const float* x = X + (size_t)row * K;
    float a0 = 0.f, a1 = 0.f;
    for (int k = lane; k < K; k += 32) {
        const float xv = x[k];
        a0 = fmaf(xv, Ws[2 * k], a0);
        a1 = fmaf(xv, Ws[2 * k + 1], a1);
    }
#pragma unroll
    for (int off = 16; off; off >>= 1) {
        a0 += __shfl_down_sync(0xffffffffu, a0, off);
        a1 += __shfl_down_sync(0xffffffffu, a1, off);
    }
    if (lane == 0) {
        out[2 * row]     = a0 + bias[0];
        out[2 * row + 1] = a1 + bias[1];
    }
}

// ---------------- launch -------------------------------------------------
extern "C" void kernel_launch(void* const* d_in, const int* in_sizes, int n_in,
                              void* d_out, int out_size) {
    const float* H   = (const float*)d_in[0];
    const float* smv = (const float*)d_in[1];
    const float* spv = (const float*)d_in[2];
    const float* W[6];
    const float* bb[6];
    for (int i = 0; i < 6; i++) {
        W[i]  = (const float*)d_in[3 + 2 * i];
        bb[i] = (const float*)d_in[4 + 2 * i];
    }
    const int* smi = (const int*)d_in[15];
    const int* spi = (const int*)d_in[16];
    float* out = (float*)d_out;

    float *bufA, *bufB;
    __nv_bfloat16 *hi, *lo, *wst;
    cudaGetSymbolAddress((void**)&bufA, g_bufA);
    cudaGetSymbolAddress((void**)&bufB, g_bufB);
    cudaGetSymbolAddress((void**)&hi, g_hi);
    cudaGetSymbolAddress((void**)&lo, g_lo);
    cudaGetSymbolAddress((void**)&wst, g_wstack);

    cudaFuncSetAttribute(gemm_mma_kernel, cudaFuncAttributeMaxDynamicSharedMemorySize, GEMM_SMEM);
    cudaFuncSetAttribute(gemm_mma64_kernel, cudaFuncAttributeMaxDynamicSharedMemorySize, GEMM_SMEM64);
    cudaFuncSetAttribute(spmm_batch_hilo_kernel, cudaFuncAttributeMaxDynamicSharedMemorySize, SPMM_SMEM);
    cudaFuncSetAttribute(spmm_batch_f32_kernel, cudaFuncAttributeMaxDynamicSharedMemorySize, SPMM_SMEM);

    const int tpb = 256;
    const int mblk = M_ROWS / 128;  // 1020

    build_csr_kernel<<<2, 256>>>(smi, smv, spi, spv);

    // all weight preps up-front into disjoint regions
    prep_w_kernel<<<(320 * 2 * 416 + tpb - 1) / tpb, tpb>>>(W[1], wst + WOFF_ENC1, 400, 300, 416, 320);
    prep_w_kernel<<<(128 * 2 * 320 + tpb - 1) / tpb, tpb>>>(W[2], wst + WOFF_ENC2, 300, 100, 320, 128);
    prep_w_kernel<<<(320 * 2 * 128 + tpb - 1) / tpb, tpb>>>(W[3], wst + WOFF_DEC0, 100, 300, 128, 320);
    prep_w_kernel<<<(448 * 2 * 320 + tpb - 1) / tpb, tpb>>>(W[4], wst + WOFF_DEC1, 300, 400, 320, 448);

    // enc0 (2->400): SpMM(sm) on d=2, fused layer -> hi/lo (Kpad=416)
    spmm_d2_kernel<<<(M_ROWS + tpb - 1) / tpb, tpb>>>(0, H, bufA, 0);
    enc0_hilo_kernel<<<(M_ROWS * 104 + tpb - 1) / tpb, tpb>>>(bufA, W[0], bb[0], hi, lo, 416);

    // enc1 (400->300), Kpad=416: BN128 x2 + BN64 remainder @256
    gemm_mma_kernel<<<dim3(mblk, 2), 256, GEMM_SMEM>>>(hi, lo, wst + WOFF_ENC1, bb[1], 0, 0, bufB, 416, 300);
    gemm_mma64_kernel<<<mblk, 256, GEMM_SMEM64>>>(hi, lo, wst + WOFF_ENC1, bb[1], 0, 0, bufB, 416, 300, 256);
    spmm_batch_hilo_kernel<<<BATCH, 256, SPMM_SMEM>>>(0, bufB, hi, lo, 300, 320, 1);

    // enc2 (300->100), Kpad=320: single BN128 tile
    gemm_mma_kernel<<<dim3(mblk, 1), 256, GEMM_SMEM>>>(hi, lo, wst + WOFF_ENC2, bb[2], 0, 0, bufA, 320, 100);
    spmm_batch_f32_kernel<<<BATCH, 256, SPMM_SMEM>>>(0, bufA, bufB, 100, 1);

    // dec0 (100->300): SpMM(sp)-first -> hi/lo (Kpad=128); GEMM mode1
    spmm_batch_hilo_kernel<<<BATCH, 256, SPMM_SMEM>>>(1, bufB, hi, lo, 100, 128, 0);
    gemm_mma_kernel<<<dim3(mblk, 2), 256, GEMM_SMEM>>>(hi, lo, wst + WOFF_DEC0, bb[3], 1, 1, bufA, 128, 300);
    gemm_mma64_kernel<<<mblk, 256, GEMM_SMEM64>>>(hi, lo, wst + WOFF_DEC0, bb[3], 1, 1, bufA, 128, 300, 256);

    // dec1 (300->400): SpMM(sp)-first -> hi/lo (Kpad=320); GEMM mode1
    spmm_batch_hilo_kernel<<<BATCH, 256, SPMM_SMEM>>>(1, bufA, hi, lo, 300, 320, 0);
    gemm_mma_kernel<<<dim3(mblk, 3), 256, GEMM_SMEM>>>(hi, lo, wst + WOFF_DEC1, bb[4], 1, 1, bufB, 320, 400);
    gemm_mma64_kernel<<<mblk, 256, GEMM_SMEM64>>>(hi, lo, wst + WOFF_DEC1, bb[4], 1, 1, bufB, 320, 400, 384);

    // dec2 (400->2): thin GEMM+bias, then SpMM(sp)+ReLU on d=2 into d_out
    gemm_thin_kernel<<<M_ROWS / 8, 256>>>(bufB, W[5], bb[5], bufA, 400);
    spmm_d2_kernel<<<(M_ROWS + tpb - 1) / tpb, tpb>>>(1, bufA, out, 1);
}

// round 16
// speedup vs baseline: 1.3595x; 1.0033x over previous
#include <cuda_runtime.h>
#include <cuda_bf16.h>
#include <cstdint>

#define N_NODES 255
#define NNZ_E   2550
#define BATCH   512
#define M_ROWS  (BATCH * N_NODES)   // 130560 (divisible by 128)
#define MAXD    400
#define MAXKPAD 448

// ---------------- device scratch (no allocations allowed) ----------------
__device__ __align__(256) float         g_bufA[M_ROWS * MAXD];
__device__ __align__(256) float         g_bufB[M_ROWS * MAXD];
__device__ __align__(256) __nv_bfloat16 g_hi[M_ROWS * MAXKPAD];
__device__ __align__(256) __nv_bfloat16 g_lo[M_ROWS * MAXKPAD];
__device__ __align__(256) __nv_bfloat16 g_wstack[720896];   // 4 layer regions
__device__ int   g_rowptr[2][N_NODES + 1];
__device__ int   g_cols[2][NNZ_E];
__device__ float g_vals[2][NNZ_E];
__device__ float g_rowsum[2][N_NODES];

// wstack offsets per layer (elements)
#define WOFF_ENC1 0        // 320 x 2*416 = 266240
#define WOFF_ENC2 266240   // 128 x 2*320 =  81920
#define WOFF_DEC0 348160   // 320 x 2*128 =  81920
#define WOFF_DEC1 430080   // 448 x 2*320 = 286720

// ================= PTX helpers =================
__device__ __forceinline__ uint32_t smem_u32(const void* p) {
    uint32_t a;
    asm("{ .reg .u64 t; cvta.to.shared.u64 t, %1; cvt.u32.u64 %0, t; }" : "=r"(a) : "l"(p));
    return a;
}
__device__ __forceinline__ void ldmx4(uint32_t& r0, uint32_t& r1, uint32_t& r2, uint32_t& r3,
                                      uint32_t addr) {
    asm volatile("ldmatrix.sync.aligned.m8n8.x4.shared.b16 {%0,%1,%2,%3}, [%4];"
                 : "=r"(r0), "=r"(r1), "=r"(r2), "=r"(r3) : "r"(addr));
}
__device__ __forceinline__ void mma16816(float* d, const uint32_t* a, uint32_t b0, uint32_t b1) {
    asm volatile(
        "mma.sync.aligned.m16n8k16.row.col.f32.bf16.bf16.f32 "
        "{%0,%1,%2,%3}, {%4,%5,%6,%7}, {%8,%9}, {%0,%1,%2,%3};"
        : "+f"(d[0]), "+f"(d[1]), "+f"(d[2]), "+f"(d[3])
        : "r"(a[0]), "r"(a[1]), "r"(a[2]), "r"(a[3]), "r"(b0), "r"(b1));
}
__device__ __forceinline__ void cpasync16(uint32_t dst, const void* src) {
    asm volatile("cp.async.cg.shared.global [%0], [%1], 16;" :: "r"(dst), "l"(src) : "memory");
}
__device__ __forceinline__ void cp_commit() {
    asm volatile("cp.async.commit_group;" ::: "memory");
}

// ---------------- deterministic COO -> CSR build (1 block per matrix) ----
__global__ void build_csr_kernel(const int* __restrict__ sm_idx, const float* __restrict__ sm_val,
                                 const int* __restrict__ sp_idx, const float* __restrict__ sp_val) {
    __shared__ int   srow[NNZ_E];
    __shared__ int   scolg[NNZ_E];
    __shared__ float sval[NNZ_E];
    __shared__ int   rptr[N_NODES + 1];
    __shared__ int   cnt[N_NODES];
    const int mat = blockIdx.x;
    const int*   idx = mat ? sp_idx : sm_idx;
    const float* val = mat ? sp_val : sm_val;
    const int t = threadIdx.x;

    for (int e = t; e < NNZ_E; e += blockDim.x) {
        srow[e]  = idx[2 * e];
        scolg[e] = idx[2 * e + 1];
        sval[e]  = val[e];
    }
    for (int i = t; i < N_NODES; i += blockDim.x) cnt[i] = 0;
    __syncthreads();
    for (int e = t; e < NNZ_E; e += blockDim.x) atomicAdd(&cnt[srow[e]], 1);
    __syncthreads();
    if (t == 0) {
        int s = 0;
        for (int i = 0; i < N_NODES; i++) { rptr[i] = s; s += cnt[i]; }
        rptr[N_NODES] = s;
    }
    __syncthreads();
    for (int i = t; i < N_NODES; i += blockDim.x) {
        int c = 0;
        float s = 0.f;
        const int base = rptr[i];
        for (int e = 0; e < NNZ_E; e++) {
            if (srow[e] == i) {
                g_cols[mat][base + c] = scolg[e];
                g_vals[mat][base + c] = sval[e];
                c++;
                s += sval[e];
            }
        }
        g_rowsum[mat][i] = s;
    }
    for (int i = t; i <= N_NODES; i += blockDim.x) g_rowptr[mat][i] = rptr[i];
}

// ---------------- SpMM, feature dim = 2 ----------------------------------
__global__ void spmm_d2_kernel(int mat, const float* __restrict__ X,
                               float* __restrict__ out, int relu) {
    const int t = blockIdx.x * blockDim.x + threadIdx.x;
    if (t >= M_ROWS) return;
    const int b = t / N_NODES;
    const int i = t - b * N_NODES;
    const int p0 = g_rowptr[mat][i], p1 = g_rowptr[mat][i + 1];
    const float2* Xb = reinterpret_cast<const float2*>(X) + (size_t)b * N_NODES;
    float a0 = 0.f, a1 = 0.f;
    for (int e = p0; e < p1; e++) {
        const float v = g_vals[mat][e];
        const float2 x = Xb[g_cols[mat][e]];
        a0 = fmaf(v, x.x, a0);
        a1 = fmaf(v, x.y, a1);
    }
    if (relu) { a0 = fmaxf(a0, 0.f); a1 = fmaxf(a1, 0.f); }
    reinterpret_cast<float2*>(out)[t] = make_float2(a0, a1);
}

// ======== per-batch smem SpMM: half-warp per row, lane = q ==============
#define SPMM_SMEM 86720
#define SM_XS   0
#define SM_COL  65280
#define SM_VAL  75480
#define SM_RP   85680

__device__ __forceinline__ void spmm_stage_csr(char* sm, int mat) {
    int*   scol = reinterpret_cast<int*>(sm + SM_COL);
    float* sval = reinterpret_cast<float*>(sm + SM_VAL);
    int*   srp  = reinterpret_cast<int*>(sm + SM_RP);
    const int tid = threadIdx.x;
    for (int e = tid; e < NNZ_E; e += 256) { scol[e] = g_cols[mat][e]; sval[e] = g_vals[mat][e]; }
    if (tid <= N_NODES) srp[tid] = g_rowptr[mat][tid];
}

__device__ __forceinline__ void spmm_stage_x(char* sm, const float* Zb, int d, int dt, int vw) {
    float4* X4 = reinterpret_cast<float4*>(sm + SM_XS);
    const int tid = threadIdx.x;
    const int vw4 = vw >> 2;
    if (vw4 < 16) {
        const int pw = 16 - vw4;
        const float4 z = make_float4(0.f, 0.f, 0.f, 0.f);
        for (int it = tid; it < N_NODES * pw; it += 256) {
            const int i = it / pw;
            const int q = vw4 + (it - i * pw);
            X4[i * 16 + q] = z;
        }
    }
    for (int it = tid; it < N_NODES * vw4; it += 256) {
        const int i = it / vw4;
        const int q = it - i * vw4;
        X4[i * 16 + q] = *reinterpret_cast<const float4*>(Zb + (size_t)i * d + dt + q * 4);
    }
}

__device__ __forceinline__ float4 spmm_gather_row(const char* sm, int i, int q, int relu) {
    const float4* X4  = reinterpret_cast<const float4*>(sm + SM_XS);
    const int*  scol  = reinterpret_cast<const int*>(sm + SM_COL);
    const float* sval = reinterpret_cast<const float*>(sm + SM_VAL);
    const int*  srp   = reinterpret_cast<const int*>(sm + SM_RP);
    const int p0 = srp[i], p1 = srp[i + 1];
    float4 acc = make_float4(0.f, 0.f, 0.f, 0.f);
    for (int e = p0; e < p1; e++) {
        const float v = sval[e];
        const int col = scol[e];
        const float4 x = X4[col * 16 + q];
        acc.x = fmaf(v, x.x, acc.x);
        acc.y = fmaf(v, x.y, acc.y);
        acc.z = fmaf(v, x.z, acc.z);
        acc.w = fmaf(v, x.w, acc.w);
    }
    if (relu) {
        acc.x = fmaxf(acc.x, 0.f); acc.y = fmaxf(acc.y, 0.f);
        acc.z = fmaxf(acc.z, 0.f); acc.w = fmaxf(acc.w, 0.f);
    }
    return acc;
}

__global__ void __launch_bounds__(256)
spmm_batch_hilo_kernel(int mat, const float* __restrict__ Z,
                       __nv_bfloat16* __restrict__ hi, __nv_bfloat16* __restrict__ lo,
                       int d, int Kpad, int relu) {
    extern __shared__ __align__(16) char sm[];
    const int b = blockIdx.x;
    const float* Zb = Z + (size_t)b * N_NODES * d;
    spmm_stage_csr(sm, mat);
    const int w = threadIdx.x >> 5;
    const int lane = threadIdx.x & 31;
    const int half = lane >> 4;
    const int q = lane & 15;
    const int ntile = Kpad >> 6;
    for (int t = 0; t < ntile; t++) {
        const int dt = t * 64;
        int vw = d - dt;
        vw = vw < 0 ? 0 : (vw > 64 ? 64 : vw);
        if (t > 0) __syncthreads();
        spmm_stage_x(sm, Zb, d, dt, vw);
        __syncthreads();
        for (int r0 = 0; r0 < 256; r0 += 16) {
            const int i = r0 + w * 2 + half;
            if (i >= N_NODES) continue;
            const float4 a = spmm_gather_row(sm, i, q, relu);
            const size_t ob = ((size_t)b * N_NODES + i) * Kpad + dt + q * 4;
            __nv_bfloat16 h[4], l[4];
            const float v[4] = { a.x, a.y, a.z, a.w };
#pragma unroll
            for (int j = 0; j < 4; j++) {
                h[j] = __float2bfloat16_rn(v[j]);
                l[j] = __float2bfloat16_rn(v[j] - __bfloat162float(h[j]));
            }
            *reinterpret_cast<uint2*>(hi + ob) = *reinterpret_cast<uint2*>(h);
            *reinterpret_cast<uint2*>(lo + ob) = *reinterpret_cast<uint2*>(l);
        }
    }
}

__global__ void __launch_bounds__(256)
spmm_batch_f32_kernel(int mat, const float* __restrict__ Z,
                      float* __restrict__ out, int d, int relu) {
    extern __shared__ __align__(16) char sm[];
    const int b = blockIdx.x;
    const float* Zb = Z + (size_t)b * N_NODES * d;
    spmm_stage_csr(sm, mat);
    const int w = threadIdx.x >> 5;
    const int lane = threadIdx.x & 31;
    const int half = lane >> 4;
    const int q = lane & 15;
    const int ntile = (d + 63) >> 6;
    for (int t = 0; t < ntile; t++) {
        const int dt = t * 64;
        int vw = d - dt;
        vw = vw > 64 ? 64 : vw;
        if (t > 0) __syncthreads();
        spmm_stage_x(sm, Zb, d, dt, vw);
        __syncthreads();
        const int vw4 = vw >> 2;
        for (int r0 = 0; r0 < 256; r0 += 16) {
            const int i = r0 + w * 2 + half;
            if (i >= N_NODES || q >= vw4) continue;
            const float4 a = spmm_gather_row(sm, i, q, relu);
            *reinterpret_cast<float4*>(out + ((size_t)b * N_NODES + i) * d + dt + q * 4) = a;
        }
    }
}

// ---------------- enc0: relu(x0*W0 + x1*W1 + rowsum*b) -> hi/lo, stride Kpad
__device__ __forceinline__ void split_store(__nv_bfloat16* hi, __nv_bfloat16* lo,
                                            size_t off, float x) {
    const __nv_bfloat16 h = __float2bfloat16_rn(x);
    hi[off] = h;
    lo[off] = __float2bfloat16_rn(x - __bfloat162float(h));
}
__global__ void enc0_hilo_kernel(const float* __restrict__ X2, const float* __restrict__ W,
                                 const float* __restrict__ b,
                                 __nv_bfloat16* __restrict__ hi, __nv_bfloat16* __restrict__ lo,
                                 int Kpad) {
    const int ng = Kpad >> 2;   // float4-groups per row (104 for 416)
    const int idx = blockIdx.x * blockDim.x + threadIdx.x;
    if (idx >= M_ROWS * ng) return;
    const int m = idx / ng;
    const int q = idx - m * ng;
    const size_t obase = (size_t)m * Kpad + q * 4;
    if (q >= 100) {
        const __nv_bfloat16 z = __float2bfloat16_rn(0.f);
#pragma unroll
        for (int j = 0; j < 4; j++) { hi[obase + j] = z; lo[obase + j] = z; }
        return;
    }
    const float2 a = reinterpret_cast<const float2*>(X2)[m];
    const float4 w0 = reinterpret_cast<const float4*>(W)[q];
    const float4 w1 = reinterpret_cast<const float4*>(W + 400)[q];
    const float4 bv = reinterpret_cast<const float4*>(b)[q];
    const float sc = g_rowsum[0][m % N_NODES];
    float o[4];
    o[0] = fmaxf(fmaf(a.x, w0.x, fmaf(a.y, w1.x, sc * bv.x)), 0.f);
    o[1] = fmaxf(fmaf(a.x, w0.y, fmaf(a.y, w1.y, sc * bv.y)), 0.f);
    o[2] = fmaxf(fmaf(a.x, w0.z, fmaf(a.y, w1.z, sc * bv.z)), 0.f);
    o[3] = fmaxf(fmaf(a.x, w0.w, fmaf(a.y, w1.w, sc * bv.w)), 0.f);
#pragma unroll
    for (int j = 0; j < 4; j++) split_store(hi, lo, obase + j, o[j]);
}

// ---------------- weight prep: W[K,N] fp32 -> dst[Npad, 2*Kpad] bf16 -----
__global__ void prep_w_kernel(const float* __restrict__ W, __nv_bfloat16* __restrict__ dst,
                              int K, int N, int Kpad, int Npad) {
    const int t = blockIdx.x * blockDim.x + threadIdx.x;
    const int total = Npad * 2 * Kpad;
    if (t >= total) return;
    const int n = t / (2 * Kpad);
    const int kk = t - n * 2 * Kpad;
    const int seg = kk / Kpad;
    const int k = kk - seg * Kpad;
    float v = 0.f;
    if (n < N && k < K) v = W[(size_t)k * N + n];
    const __nv_bfloat16 h = __float2bfloat16_rn(v);
    dst[t] = (seg == 1) ? __float2bfloat16_rn(v - __bfloat162float(h)) : h;
}

// ---------------- mma.sync bf16 GEMM, chunk-major 3-term, BN=128 ---------
// GRID: blockIdx.x = n-block (FAST), blockIdx.y = m-tile. All n-blocks of an
// m-tile are co-resident -> A tile is L2-shared, A DRAM traffic ~1x not ~3-4x.
#define ASTRIDE 80
#define GTILE   (128 * ASTRIDE)             // 10240
#define GSTAGE  (4 * GTILE)                 // Ahi Alo Bhi Blo
#define GEMM_SMEM (2 * GSTAGE)              // 81920

__global__ void __launch_bounds__(256, 2)
gemm_mma_kernel(const __nv_bfloat16* __restrict__ Ahi, const __nv_bfloat16* __restrict__ Alo,
                const __nv_bfloat16* __restrict__ Wst, const float* __restrict__ bias,
                int mat, int mode, float* __restrict__ C, int Kpad, int N) {
    extern __shared__ __align__(128) char gsm[];
    const uint32_t sbase = smem_u32(gsm);

    const int tid = threadIdx.x;
    const int lane = tid & 31;
    const int w = tid >> 5;
    const int warpM = (w & 3) * 32;
    const int warpN = (w >> 2) * 64;
    const int mBase = blockIdx.y * 128;   // swapped: m on slow axis
    const int nBase = blockIdx.x * 128;   // n on fast axis

    float acc[2][8][4];
#pragma unroll
    for (int i = 0; i < 2; i++)
#pragma unroll
        for (int j = 0; j < 8; j++)
#pragma unroll
            for (int q = 0; q < 4; q++) acc[i][j][q] = 0.f;

    const int arow = (lane & 7) + ((lane >> 3) & 1) * 8;
    const int acol = (lane >> 4) * 8;
    uint32_t aoff[2];
#pragma unroll
    for (int mt = 0; mt < 2; mt++)
        aoff[mt] = (uint32_t)((warpM + mt * 16 + arow) * ASTRIDE + acol * 2);
    const int bn = (lane >> 4) * 8 + (lane & 7);
    const int bk = ((lane >> 3) & 1) * 8;
    uint32_t boff[4];
#pragma unroll
    for (int j = 0; j < 4; j++)
        boff[j] = (uint32_t)((warpN + j * 16 + bn) * ASTRIDE + bk * 2);

    const int ldrow = tid >> 1;
    const int ch0 = (tid & 1) * 2;
    const uint32_t stoff = (uint32_t)(ldrow * ASTRIDE + ch0 * 16);
    const int wrow = 2 * Kpad;
    const int nch = Kpad >> 5;
    const __nv_bfloat16* ArowH = Ahi + (size_t)(mBase + ldrow) * Kpad + ch0 * 8;
    const __nv_bfloat16* ArowL = Alo + (size_t)(mBase + ldrow) * Kpad + ch0 * 8;
    const __nv_bfloat16* BrowH = Wst + (size_t)(nBase + ldrow) * wrow + ch0 * 8;
    const __nv_bfloat16* BrowL = BrowH + Kpad;

    auto issue = [&](int c, int st) {
        const int k0 = c * 32;
        const uint32_t sb = sbase + st * GSTAGE + stoff;
        cpasync16(sb,                  ArowH + k0);
        cpasync16(sb + 16,             ArowH + k0 + 8);
        cpasync16(sb + GTILE,          ArowL + k0);
        cpasync16(sb + GTILE + 16,     ArowL + k0 + 8);
        cpasync16(sb + 2 * GTILE,      BrowH + k0);
        cpasync16(sb + 2 * GTILE + 16, BrowH + k0 + 8);
        cpasync16(sb + 3 * GTILE,      BrowL + k0);
        cpasync16(sb + 3 * GTILE + 16, BrowL + k0 + 8);
        cp_commit();
    };

    issue(0, 0);
    for (int c = 0; c < nch; c++) {
        const int st = c & 1;
        asm volatile("cp.async.wait_group 0;" ::: "memory");
        __syncthreads();
        if (c + 1 < nch) issue(c + 1, st ^ 1);

        const uint32_t stage = sbase + st * GSTAGE;
#pragma unroll
        for (int ks = 0; ks < 2; ks++) {
            uint32_t afH[2][4], afL[2][4];
#pragma unroll
            for (int mt = 0; mt < 2; mt++) {
                ldmx4(afH[mt][0], afH[mt][1], afH[mt][2], afH[mt][3],
                      stage + aoff[mt] + ks * 32);
                ldmx4(afL[mt][0], afL[mt][1], afL[mt][2], afL[mt][3],
                      stage + GTILE + aoff[mt] + ks * 32);
            }
#pragma unroll
            for (int j = 0; j < 4; j++) {
                uint32_t b0, b1, b2, b3;
                ldmx4(b0, b1, b2, b3, stage + 2 * GTILE + boff[j] + ks * 32);
#pragma unroll
                for (int mt = 0; mt < 2; mt++) {
                    mma16816(acc[mt][2 * j],     afH[mt], b0, b1);
                    mma16816(acc[mt][2 * j + 1], afH[mt], b2, b3);
                    mma16816(acc[mt][2 * j],     afL[mt], b0, b1);
                    mma16816(acc[mt][2 * j + 1], afL[mt], b2, b3);
                }
                ldmx4(b0, b1, b2, b3, stage + 3 * GTILE + boff[j] + ks * 32);
#pragma unroll
                for (int mt = 0; mt < 2; mt++) {
                    mma16816(acc[mt][2 * j],     afH[mt], b0, b1);
                    mma16816(acc[mt][2 * j + 1], afH[mt], b2, b3);
                }
            }
        }
    }

#pragma unroll
    for (int mt = 0; mt < 2; mt++) {
        const int r0 = mBase + warpM + mt * 16 + (lane >> 2);
        const int r1 = r0 + 8;
        const float s0 = (mode == 1) ? g_rowsum[mat][r0 % N_NODES] : 1.f;
        const float s1 = (mode == 1) ? g_rowsum[mat][r1 % N_NODES] : 1.f;
#pragma unroll
        for (int nt = 0; nt < 8; nt++) {
            const int n = nBase + warpN + nt * 8 + (lane & 3) * 2;
            if (n >= N) continue;
            const float b0 = bias[n], b1 = bias[n + 1];
            float o0 = acc[mt][nt][0] + b0 * s0;
            float o1 = acc[mt][nt][1] + b1 * s0;
            float o2 = acc[mt][nt][2] + b0 * s1;
            float o3 = acc[mt][nt][3] + b1 * s1;
            if (mode == 1) {
                o0 = fmaxf(o0, 0.f); o1 = fmaxf(o1, 0.f);
                o2 = fmaxf(o2, 0.f); o3 = fmaxf(o3, 0.f);
            }
            *reinterpret_cast<float2*>(C + (size_t)r0 * N + n) = make_float2(o0, o1);
            *reinterpret_cast<float2*>(C + (size_t)r1 * N + n) = make_float2(o2, o3);
        }
    }
}

// ---------------- BN=64 remainder GEMM: 8 warps stacked in M -------------
#define BTILE64 (64 * ASTRIDE)                      // 5120
#define GSTAGE64 (2 * GTILE + 2 * BTILE64)          // 30720
#define GEMM_SMEM64 (2 * GSTAGE64)                  // 61440

__global__ void __launch_bounds__(256, 2)
gemm_mma64_kernel(const __nv_bfloat16* __restrict__ Ahi, const __nv_bfloat16* __restrict__ Alo,
                  const __nv_bfloat16* __restrict__ Wst, const float* __restrict__ bias,
                  int mat, int mode, float* __restrict__ C, int Kpad, int N, int n0) {
    extern __shared__ __align__(128) char gsm[];
    const uint32_t sbase = smem_u32(gsm);

    const int tid = threadIdx.x;
    const int lane = tid & 31;
    const int w = tid >> 5;
    const int warpM = w * 16;          // 8 warps x 16 rows = 128
    const int mBase = blockIdx.x * 128;

    float acc[8][4];
#pragma unroll
    for (int j = 0; j < 8; j++)
#pragma unroll
        for (int q = 0; q < 4; q++) acc[j][q] = 0.f;

    const int arow = (lane & 7) + ((lane >> 3) & 1) * 8;
    const int acol = (lane >> 4) * 8;
    const uint32_t aoff = (uint32_t)((warpM + arow) * ASTRIDE + acol * 2);
    const int bn = (lane >> 4) * 8 + (lane & 7);
    const int bk = ((lane >> 3) & 1) * 8;
    uint32_t boff[4];
#pragma unroll
    for (int j = 0; j < 4; j++)
        boff[j] = (uint32_t)((j * 16 + bn) * ASTRIDE + bk * 2);

    const int ldrow = tid >> 1;
    const int ch0 = (tid & 1) * 2;
    const uint32_t stoffA = (uint32_t)(ldrow * ASTRIDE + ch0 * 16);
    const int wrow = 2 * Kpad;
    const int nch = Kpad >> 5;
    const __nv_bfloat16* ArowH = Ahi + (size_t)(mBase + ldrow) * Kpad + ch0 * 8;
    const __nv_bfloat16* ArowL = Alo + (size_t)(mBase + ldrow) * Kpad + ch0 * 8;
    const int brow = tid >> 1;         // 0..63 when tid<128
    const uint32_t stoffB = (uint32_t)(brow * ASTRIDE + ch0 * 16);
    const __nv_bfloat16* BrowH = Wst + (size_t)(n0 + brow) * wrow + ch0 * 8;
    const __nv_bfloat16* BrowL = BrowH + Kpad;

    auto issue = [&](int c, int st) {
        const int k0 = c * 32;
        const uint32_t sb = sbase + st * GSTAGE64;
        cpasync16(sb + stoffA,               ArowH + k0);
        cpasync16(sb + stoffA + 16,          ArowH + k0 + 8);
        cpasync16(sb + GTILE + stoffA,       ArowL + k0);
        cpasync16(sb + GTILE + stoffA + 16,  ArowL + k0 + 8);
        if (tid < 128) {
            cpasync16(sb + 2 * GTILE + stoffB,                BrowH + k0);
            cpasync16(sb + 2 * GTILE + stoffB + 16,           BrowH + k0 + 8);
            cpasync16(sb + 2 * GTILE + BTILE64 + stoffB,      BrowL + k0);
            cpasync16(sb + 2 * GTILE + BTILE64 + stoffB + 16, BrowL + k0 + 8);
        }
        cp_commit();
    };

    issue(0, 0);
    for (int c = 0; c < nch; c++) {
        const int st = c & 1;
        asm volatile("cp.async.wait_group 0;" ::: "memory");
        __syncthreads();
        if (c + 1 < nch) issue(c + 1, st ^ 1);

        const uint32_t stage = sbase + st * GSTAGE64;
#pragma unroll
        for (int ks = 0; ks < 2; ks++) {
            uint32_t afH[4], afL[4];
            ldmx4(afH[0], afH[1], afH[2], afH[3], stage + aoff + ks * 32);
            ldmx4(afL[0], afL[1], afL[2], afL[3], stage + GTILE + aoff + ks * 32);
#pragma unroll
            for (int j = 0; j < 4; j++) {
                uint32_t b0, b1, b2, b3;
                ldmx4(b0, b1, b2, b3, stage + 2 * GTILE + boff[j] + ks * 32);
                mma16816(acc[2 * j],     afH, b0, b1);
                mma16816(acc[2 * j + 1], afH, b2, b3);
                mma16816(acc[2 * j],     afL, b0, b1);
                mma16816(acc[2 * j + 1], afL, b2, b3);
                ldmx4(b0, b1, b2, b3, stage + 2 * GTILE + BTILE64 + boff[j] + ks * 32);
                mma16816(acc[2 * j],     afH, b0, b1);
                mma16816(acc[2 * j + 1], afH, b2, b3);
            }
        }
    }

    const int r0 = mBase + warpM + (lane >> 2);
    const int r1 = r0 + 8;
    const float s0 = (mode == 1) ? g_rowsum[mat][r0 % N_NODES] : 1.f;
    const float s1 = (mode == 1) ? g_rowsum[mat][r1 % N_NODES] : 1.f;
#pragma unroll
    for (int nt = 0; nt < 8; nt++) {
        const int n = n0 + nt * 8 + (lane & 3) * 2;
        if (n >= N) continue;
        const float b0 = bias[n], b1 = bias[n + 1];
        float o0 = acc[nt][0] + b0 * s0;
        float o1 = acc[nt][1] + b1 * s0;
        float o2 = acc[nt][2] + b0 * s1;
        float o3 = acc[nt][3] + b1 * s1;
        if (mode == 1) {
            o0 = fmaxf(o0, 0.f); o1 = fmaxf(o1, 0.f);
            o2 = fmaxf(o2, 0.f); o3 = fmaxf(o3, 0.f);
        }
        *reinterpret_cast<float2*>(C + (size_t)r0 * N + n) = make_float2(o0, o1);
        *reinterpret_cast<float2*>(C + (size_t)r1 * N + n) = make_float2(o2, o3);
    }
}

// ---------------- thin GEMM for N=2 (dec2): warp per row -----------------
__global__ void gemm_thin_kernel(const float* __restrict__ X, const float* __restrict__ Wt,
                                 const float* __restrict__ bias, float* __restrict__ out, int K) {
    __shared__ float Ws[2 * MAXD];
    for (int i = threadIdx.x; i < 2 * K; i += blockDim.x) Ws[i] = Wt[i];
    __syncthreads();
    const int warp = threadIdx.x >> 5, lane = threadIdx.x & 31;
    const int row = blockIdx.x * 8 + warp;
    if (row >= M_ROWS) return;
    const float* x = X + (size_t)row * K;
    float a0 = 0.f, a1 = 0.f;
    for (int k = lane; k < K; k += 32) {
        const float xv = x[k];
        a0 = fmaf(xv, Ws[2 * k], a0);
        a1 = fmaf(xv, Ws[2 * k + 1], a1);
    }
#pragma unroll
    for (int off = 16; off; off >>= 1) {
        a0 += __shfl_down_sync(0xffffffffu, a0, off);
        a1 += __shfl_down_sync(0xffffffffu, a1, off);
    }
    if (lane == 0) {
        out[2 * row]     = a0 + bias[0];
        out[2 * row + 1] = a1 + bias[1];
    }
}

// ---------------- launch -------------------------------------------------
extern "C" void kernel_launch(void* const* d_in, const int* in_sizes, int n_in,
                              void* d_out, int out_size) {
    const float* H   = (const float*)d_in[0];
    const float* smv = (const float*)d_in[1];
    const float* spv = (const float*)d_in[2];
    const float* W[6];
    const float* bb[6];
    for (int i = 0; i < 6; i++) {
        W[i]  = (const float*)d_in[3 + 2 * i];
        bb[i] = (const float*)d_in[4 + 2 * i];
    }
    const int* smi = (const int*)d_in[15];
    const int* spi = (const int*)d_in[16];
    float* out = (float*)d_out;

    float *bufA, *bufB;
    __nv_bfloat16 *hi, *lo, *wst;
    cudaGetSymbolAddress((void**)&bufA, g_bufA);
    cudaGetSymbolAddress((void**)&bufB, g_bufB);
    cudaGetSymbolAddress((void**)&hi, g_hi);
    cudaGetSymbolAddress((void**)&lo, g_lo);
    cudaGetSymbolAddress((void**)&wst, g_wstack);

    cudaFuncSetAttribute(gemm_mma_kernel, cudaFuncAttributeMaxDynamicSharedMemorySize, GEMM_SMEM);
    cudaFuncSetAttribute(gemm_mma64_kernel, cudaFuncAttributeMaxDynamicSharedMemorySize, GEMM_SMEM64);
    cudaFuncSetAttribute(spmm_batch_hilo_kernel, cudaFuncAttributeMaxDynamicSharedMemorySize, SPMM_SMEM);
    cudaFuncSetAttribute(spmm_batch_f32_kernel, cudaFuncAttributeMaxDynamicSharedMemorySize, SPMM_SMEM);

    const int tpb = 256;
    const int mblk = M_ROWS / 128;  // 1020

    build_csr_kernel<<<2, 256>>>(smi, smv, spi, spv);

    // all weight preps up-front into disjoint regions
    prep_w_kernel<<<(320 * 2 * 416 + tpb - 1) / tpb, tpb>>>(W[1], wst + WOFF_ENC1, 400, 300, 416, 320);
    prep_w_kernel<<<(128 * 2 * 320 + tpb - 1) / tpb, tpb>>>(W[2], wst + WOFF_ENC2, 300, 100, 320, 128);
    prep_w_kernel<<<(320 * 2 * 128 + tpb - 1) / tpb, tpb>>>(W[3], wst + WOFF_DEC0, 100, 300, 128, 320);
    prep_w_kernel<<<(448 * 2 * 320 + tpb - 1) / tpb, tpb>>>(W[4], wst + WOFF_DEC1, 300, 400, 320, 448);

    // enc0 (2->400): SpMM(sm) on d=2, fused layer -> hi/lo (Kpad=416)
    spmm_d2_kernel<<<(M_ROWS + tpb - 1) / tpb, tpb>>>(0, H, bufA, 0);
    enc0_hilo_kernel<<<(M_ROWS * 104 + tpb - 1) / tpb, tpb>>>(bufA, W[0], bb[0], hi, lo, 416);

    // enc1 (400->300), Kpad=416: BN128 x2 (n fast) + BN64 remainder @256
    gemm_mma_kernel<<<dim3(2, mblk), 256, GEMM_SMEM>>>(hi, lo, wst + WOFF_ENC1, bb[1], 0, 0, bufB, 416, 300);
    gemm_mma64_kernel<<<mblk, 256, GEMM_SMEM64>>>(hi, lo, wst + WOFF_ENC1, bb[1], 0, 0, bufB, 416, 300, 256);
    spmm_batch_hilo_kernel<<<BATCH, 256, SPMM_SMEM>>>(0, bufB, hi, lo, 300, 320, 1);

    // enc2 (300->100), Kpad=320: single BN128 tile
    gemm_mma_kernel<<<dim3(1, mblk), 256, GEMM_SMEM>>>(hi, lo, wst + WOFF_ENC2, bb[2], 0, 0, bufA, 320, 100);
    spmm_batch_f32_kernel<<<BATCH, 256, SPMM_SMEM>>>(0, bufA, bufB, 100, 1);

    // dec0 (100->300): SpMM(sp)-first -> hi/lo (Kpad=128); GEMM mode1
    spmm_batch_hilo_kernel<<<BATCH, 256, SPMM_SMEM>>>(1, bufB, hi, lo, 100, 128, 0);
    gemm_mma_kernel<<<dim3(2, mblk), 256, GEMM_SMEM>>>(hi, lo, wst + WOFF_DEC0, bb[3], 1, 1, bufA, 128, 300);
    gemm_mma64_kernel<<<mblk, 256, GEMM_SMEM64>>>(hi, lo, wst + WOFF_DEC0, bb[3], 1, 1, bufA, 128, 300, 256);

    // dec1 (300->400): SpMM(sp)-first -> hi/lo (Kpad=320); GEMM mode1
    spmm_batch_hilo_kernel<<<BATCH, 256, SPMM_SMEM>>>(1, bufA, hi, lo, 300, 320, 0);
    gemm_mma_kernel<<<dim3(3, mblk), 256, GEMM_SMEM>>>(hi, lo, wst + WOFF_DEC1, bb[4], 1, 1, bufB, 320, 400);
    gemm_mma64_kernel<<<mblk, 256, GEMM_SMEM64>>>(hi, lo, wst + WOFF_DEC1, bb[4], 1, 1, bufB, 320, 400, 384);

    // dec2 (400->2): thin GEMM+bias, then SpMM(sp)+ReLU on d=2 into d_out
    gemm_thin_kernel<<<M_ROWS / 8, 256>>>(bufB, W[5], bb[5], bufA, 400);
    spmm_d2_kernel<<<(M_ROWS + tpb - 1) / tpb, tpb>>>(1, bufA, out, 1);
}